// round 1
// baseline (speedup 1.0000x reference)
#include <cuda_runtime.h>

// Problem constants
//  x: [4, 2048, 1024], w*: [1024,1024] (out = x @ w.T + b), H=16, d_k=64
#define CEXP 0.18033688011112042f   // 0.125 * log2(e)   (1/sqrt(64) folded into exp2)

// Scratch: Q, K, V, attn-out in [b][h][s][d] layout (4*16*2048*64 = 8388608 floats each)
static __device__ float g_q[8388608];
static __device__ float g_k[8388608];
static __device__ float g_v[8388608];
static __device__ float g_ao[8388608];

// FFMA-only 2^t (t <= 0 here). MUFU.EX2 at rt_SMSP=8 would cost ~2ms for the
// 268M softmax exps in this problem; this polynomial runs on the FMA pipe.
__device__ __forceinline__ float fexp2f(float t) {
    t = fmaxf(t, -126.0f);
    const float r = t + 12582912.0f;              // round-to-nearest via magic
    const float f = t - (r - 12582912.0f);        // f in [-0.5, 0.5]
    const int   n = __float_as_int(r) - 0x4B400000;
    float p =        1.3333558146428443e-3f;
    p = fmaf(p, f,   9.6181291076284771e-3f);
    p = fmaf(p, f,   5.5504108664821580e-2f);
    p = fmaf(p, f,   2.4022650695910071e-1f);
    p = fmaf(p, f,   6.9314718055994531e-1f);
    p = fmaf(p, f,   1.0f);
    return __int_as_float(__float_as_int(p) + (n << 23));
}

// ---------------------------------------------------------------------------
// GEMM: C[m,n] = sum_k A[m,k] * W[n,k] + bias[n]    (M=8192, N=K=1024)
// A_HEADS: A is read from [b][h][s][d] layout (attention output)
// C_HEADS: C is written to [b][h][s][d] layout (Q/K/V projections)
// 128x128 tile, BK=16, 256 threads, 8x8 per-thread micro-tile.
// ---------------------------------------------------------------------------
template<bool A_HEADS, bool C_HEADS>
__global__ void __launch_bounds__(256, 2)
gemm_nt(const float* __restrict__ A, const float* __restrict__ W,
        const float* __restrict__ bias, float* __restrict__ C)
{
    constexpr int K = 1024;
    constexpr int STR = 132;                       // 128 + 4 pad (16B-aligned)
    __shared__ float As[16 * STR];
    __shared__ float Bs[16 * STR];

    const int tid = threadIdx.x;
    const int ty = tid >> 4, tx = tid & 15;
    const int m0 = blockIdx.y << 7, n0 = blockIdx.x << 7;

    float acc[8][8];
#pragma unroll
    for (int i = 0; i < 8; i++)
#pragma unroll
        for (int j = 0; j < 8; j++) acc[i][j] = 0.f;

    for (int k0 = 0; k0 < K; k0 += 16) {
        __syncthreads();
#pragma unroll
        for (int it = 0; it < 2; it++) {
            const int idx = tid + it * 256;
            const int row = idx >> 2;              // 0..127
            const int kc  = (idx & 3) << 2;        // 0,4,8,12
            float4 av;
            if (A_HEADS) {
                const int m = m0 + row, k = k0 + kc;
                const int b = m >> 11, s = m & 2047, h = k >> 6, d = k & 63;
                av = *(const float4*)(A + (size_t)((((b << 4) + h) << 11) + s) * 64 + d);
            } else {
                av = *(const float4*)(A + (size_t)(m0 + row) * K + k0 + kc);
            }
            As[(kc + 0) * STR + row] = av.x;
            As[(kc + 1) * STR + row] = av.y;
            As[(kc + 2) * STR + row] = av.z;
            As[(kc + 3) * STR + row] = av.w;
            const float4 wv = *(const float4*)(W + (size_t)(n0 + row) * K + k0 + kc);
            Bs[(kc + 0) * STR + row] = wv.x;
            Bs[(kc + 1) * STR + row] = wv.y;
            Bs[(kc + 2) * STR + row] = wv.z;
            Bs[(kc + 3) * STR + row] = wv.w;
        }
        __syncthreads();
#pragma unroll
        for (int kk = 0; kk < 16; kk++) {
            const float4 a0 = *(const float4*)(As + kk * STR + ty * 8);
            const float4 a1 = *(const float4*)(As + kk * STR + ty * 8 + 4);
            const float4 b0 = *(const float4*)(Bs + kk * STR + tx * 8);
            const float4 b1 = *(const float4*)(Bs + kk * STR + tx * 8 + 4);
            const float a[8] = {a0.x, a0.y, a0.z, a0.w, a1.x, a1.y, a1.z, a1.w};
            const float b[8] = {b0.x, b0.y, b0.z, b0.w, b1.x, b1.y, b1.z, b1.w};
#pragma unroll
            for (int i = 0; i < 8; i++)
#pragma unroll
                for (int j = 0; j < 8; j++)
                    acc[i][j] = fmaf(a[i], b[j], acc[i][j]);
        }
    }

#pragma unroll
    for (int i = 0; i < 8; i++) {
        const int m = m0 + ty * 8 + i;
#pragma unroll
        for (int j4 = 0; j4 < 2; j4++) {
            const int n = n0 + tx * 8 + j4 * 4;
            float4 o;
            o.x = acc[i][j4 * 4 + 0] + bias[n + 0];
            o.y = acc[i][j4 * 4 + 1] + bias[n + 1];
            o.z = acc[i][j4 * 4 + 2] + bias[n + 2];
            o.w = acc[i][j4 * 4 + 3] + bias[n + 3];
            if (C_HEADS) {
                const int b = m >> 11, s = m & 2047, h = n >> 6, d = n & 63;
                *(float4*)(C + (size_t)((((b << 4) + h) << 11) + s) * 64 + d) = o;
            } else {
                *(float4*)(C + (size_t)m * 1024 + n) = o;
            }
        }
    }
}

// ---------------------------------------------------------------------------
// Flash attention: one block per (bh, 128-query tile). Online softmax over
// 16 KV tiles of 128 keys. d_k = 64. 256 threads (16x16), S-tile 8x8/thread,
// O-tile 8x4/thread. Scale 1/8 folded into the exp2 constant.
// ---------------------------------------------------------------------------
__global__ void __launch_bounds__(256, 1)
flash_attn(const float* __restrict__ Q, const float* __restrict__ K,
           const float* __restrict__ V, float* __restrict__ O)
{
    extern __shared__ float sm[];
    float* Qs = sm;                     // [64][132]   (d-major, transposed)
    float* Ks = sm + 64 * 132;          // [64][132]
    float* Vs = sm + 2 * 64 * 132;      // [128][64]
    float* Ps = Vs + 128 * 64;          // [128][128]

    const int tid = threadIdx.x;
    const int ty = tid >> 4, tx = tid & 15;
    const int q0 = blockIdx.x << 7;
    const size_t base = (size_t)blockIdx.y * (2048 * 64);
    const float* Qb = Q + base;
    const float* Kb = K + base;
    const float* Vb = V + base;
    float* Ob = O + base;

    // Load Q tile transposed: Qs[d][q]
#pragma unroll
    for (int it = 0; it < 8; it++) {
        const int idx = tid + it * 256;
        const int row = idx >> 4;               // 0..127
        const int d4  = (idx & 15) << 2;        // 0..60
        const float4 qv = *(const float4*)(Qb + (size_t)(q0 + row) * 64 + d4);
        Qs[(d4 + 0) * 132 + row] = qv.x;
        Qs[(d4 + 1) * 132 + row] = qv.y;
        Qs[(d4 + 2) * 132 + row] = qv.z;
        Qs[(d4 + 3) * 132 + row] = qv.w;
    }

    float m_r[8], l_r[8], oa[8][4];
#pragma unroll
    for (int i = 0; i < 8; i++) {
        m_r[i] = -3.0e38f;
        l_r[i] = 0.f;
#pragma unroll
        for (int c = 0; c < 4; c++) oa[i][c] = 0.f;
    }

    for (int t = 0; t < 16; t++) {
        const int k0 = t << 7;
        __syncthreads();                        // protect Ks/Vs/Ps from prev iter
#pragma unroll
        for (int it = 0; it < 8; it++) {
            const int idx = tid + it * 256;
            const int row = idx >> 4;
            const int d4  = (idx & 15) << 2;
            const float4 kv = *(const float4*)(Kb + (size_t)(k0 + row) * 64 + d4);
            Ks[(d4 + 0) * 132 + row] = kv.x;
            Ks[(d4 + 1) * 132 + row] = kv.y;
            Ks[(d4 + 2) * 132 + row] = kv.z;
            Ks[(d4 + 3) * 132 + row] = kv.w;
            *(float4*)(Vs + row * 64 + d4) =
                *(const float4*)(Vb + (size_t)(k0 + row) * 64 + d4);
        }
        __syncthreads();

        // S = Q K^T  (raw scores; 1/8 scale folded into CEXP)
        float s[8][8];
#pragma unroll
        for (int i = 0; i < 8; i++)
#pragma unroll
            for (int j = 0; j < 8; j++) s[i][j] = 0.f;

#pragma unroll 4
        for (int d = 0; d < 64; d++) {
            const float4 a0 = *(const float4*)(Qs + d * 132 + ty * 8);
            const float4 a1 = *(const float4*)(Qs + d * 132 + ty * 8 + 4);
            const float4 b0 = *(const float4*)(Ks + d * 132 + tx * 8);
            const float4 b1 = *(const float4*)(Ks + d * 132 + tx * 8 + 4);
            const float a[8] = {a0.x, a0.y, a0.z, a0.w, a1.x, a1.y, a1.z, a1.w};
            const float b[8] = {b0.x, b0.y, b0.z, b0.w, b1.x, b1.y, b1.z, b1.w};
#pragma unroll
            for (int i = 0; i < 8; i++)
#pragma unroll
                for (int j = 0; j < 8; j++)
                    s[i][j] = fmaf(a[i], b[j], s[i][j]);
        }

        // Online softmax update per row (16 lanes share each row group)
#pragma unroll
        for (int i = 0; i < 8; i++) {
            float mt = s[i][0];
#pragma unroll
            for (int j = 1; j < 8; j++) mt = fmaxf(mt, s[i][j]);
#pragma unroll
            for (int off = 8; off >= 1; off >>= 1)
                mt = fmaxf(mt, __shfl_xor_sync(0xffffffffu, mt, off));
            const float mn = fmaxf(m_r[i], mt);
            const float alpha = fexp2f((m_r[i] - mn) * CEXP);
            m_r[i] = mn;
#pragma unroll
            for (int c = 0; c < 4; c++) oa[i][c] *= alpha;
            float rs = 0.f;
#pragma unroll
            for (int j = 0; j < 8; j++) {
                const float p = fexp2f((s[i][j] - mn) * CEXP);
                s[i][j] = p;
                rs += p;
            }
#pragma unroll
            for (int off = 8; off >= 1; off >>= 1)
                rs += __shfl_xor_sync(0xffffffffu, rs, off);
            l_r[i] = l_r[i] * alpha + rs;
        }

        // Stage P to smem
#pragma unroll
        for (int i = 0; i < 8; i++) {
            *(float4*)(Ps + (ty * 8 + i) * 128 + tx * 8) =
                make_float4(s[i][0], s[i][1], s[i][2], s[i][3]);
            *(float4*)(Ps + (ty * 8 + i) * 128 + tx * 8 + 4) =
                make_float4(s[i][4], s[i][5], s[i][6], s[i][7]);
        }
        __syncthreads();

        // O += P V
#pragma unroll 2
        for (int kk = 0; kk < 128; kk += 4) {
            float4 vv[4];
#pragma unroll
            for (int c = 0; c < 4; c++)
                vv[c] = *(const float4*)(Vs + (kk + c) * 64 + tx * 4);
#pragma unroll
            for (int i = 0; i < 8; i++) {
                const float4 pp = *(const float4*)(Ps + (ty * 8 + i) * 128 + kk);
                oa[i][0] = fmaf(pp.x, vv[0].x, fmaf(pp.y, vv[1].x,
                           fmaf(pp.z, vv[2].x, fmaf(pp.w, vv[3].x, oa[i][0]))));
                oa[i][1] = fmaf(pp.x, vv[0].y, fmaf(pp.y, vv[1].y,
                           fmaf(pp.z, vv[2].y, fmaf(pp.w, vv[3].y, oa[i][1]))));
                oa[i][2] = fmaf(pp.x, vv[0].z, fmaf(pp.y, vv[1].z,
                           fmaf(pp.z, vv[2].z, fmaf(pp.w, vv[3].z, oa[i][2]))));
                oa[i][3] = fmaf(pp.x, vv[0].w, fmaf(pp.y, vv[1].w,
                           fmaf(pp.z, vv[2].w, fmaf(pp.w, vv[3].w, oa[i][3]))));
            }
        }
    }

#pragma unroll
    for (int i = 0; i < 8; i++) {
        const float inv = 1.0f / l_r[i];
        const float4 o = make_float4(oa[i][0] * inv, oa[i][1] * inv,
                                     oa[i][2] * inv, oa[i][3] * inv);
        *(float4*)(Ob + (size_t)(q0 + ty * 8 + i) * 64 + tx * 4) = o;
    }
}

// ---------------------------------------------------------------------------
extern "C" void kernel_launch(void* const* d_in, const int* in_sizes, int n_in,
                              void* d_out, int out_size)
{
    const float* x  = (const float*)d_in[0];
    const float* wq = (const float*)d_in[1];
    const float* bq = (const float*)d_in[2];
    const float* wk = (const float*)d_in[3];
    const float* bk = (const float*)d_in[4];
    const float* wv = (const float*)d_in[5];
    const float* bv = (const float*)d_in[6];
    const float* wo = (const float*)d_in[7];
    const float* bo = (const float*)d_in[8];
    float* out = (float*)d_out;

    float *q, *k, *v, *ao;
    cudaGetSymbolAddress((void**)&q,  g_q);
    cudaGetSymbolAddress((void**)&k,  g_k);
    cudaGetSymbolAddress((void**)&v,  g_v);
    cudaGetSymbolAddress((void**)&ao, g_ao);

    const int FLASH_SMEM = (2 * 64 * 132 + 128 * 64 + 128 * 128) * (int)sizeof(float);
    cudaFuncSetAttribute(flash_attn, cudaFuncAttributeMaxDynamicSharedMemorySize,
                         FLASH_SMEM);

    const dim3 gg(8, 64);      // N/128, M/128
    gemm_nt<false, true><<<gg, 256>>>(x, wq, bq, q);
    gemm_nt<false, true><<<gg, 256>>>(x, wk, bk, k);
    gemm_nt<false, true><<<gg, 256>>>(x, wv, bv, v);
    flash_attn<<<dim3(16, 64), 256, FLASH_SMEM>>>(q, k, v, ao);
    gemm_nt<true, false><<<gg, 256>>>(ao, wo, bo, out);
}

// round 3
// speedup vs baseline: 6.0419x; 6.0419x over previous
#include <cuda_runtime.h>
#include <cuda_fp16.h>
#include <cstdint>

#define CEXP 0.18033688011112042f   // 0.125 * log2(e)

// fp16 scratch
static __device__ __align__(16) __half g_xh[8388608];   // x as fp16
static __device__ __align__(16) __half g_wh[4194304];   // wq|wk|wv|wo as fp16
static __device__ __align__(16) __half g_qh[8388608];   // [b][h][s][d]
static __device__ __align__(16) __half g_kh[8388608];
static __device__ __align__(16) __half g_vh[8388608];
static __device__ __align__(16) __half g_aoh[8388608];  // [b][s][h*d]

// ---------------------------------------------------------------------------
__device__ __forceinline__ uint32_t smem_u32(const void* p) {
    uint32_t a;
    asm("{ .reg .u64 t; cvta.to.shared.u64 t, %1; cvt.u32.u64 %0, t; }" : "=r"(a) : "l"(p));
    return a;
}
#define CP16(s, g) asm volatile("cp.async.cg.shared.global [%0], [%1], 16;" :: "r"(s), "l"(g))
#define CP_COMMIT() asm volatile("cp.async.commit_group;" ::: "memory")
#define CP_WAIT0()  asm volatile("cp.async.wait_group 0;" ::: "memory")
#define CP_WAIT1()  asm volatile("cp.async.wait_group 1;" ::: "memory")

__device__ __forceinline__ void ldsm4(uint32_t& r0, uint32_t& r1, uint32_t& r2, uint32_t& r3,
                                      uint32_t a) {
    asm volatile("ldmatrix.sync.aligned.m8n8.x4.shared.b16 {%0,%1,%2,%3}, [%4];"
                 : "=r"(r0), "=r"(r1), "=r"(r2), "=r"(r3) : "r"(a));
}
__device__ __forceinline__ void ldsm4t(uint32_t& r0, uint32_t& r1, uint32_t& r2, uint32_t& r3,
                                       uint32_t a) {
    asm volatile("ldmatrix.sync.aligned.m8n8.x4.trans.shared.b16 {%0,%1,%2,%3}, [%4];"
                 : "=r"(r0), "=r"(r1), "=r"(r2), "=r"(r3) : "r"(a));
}
__device__ __forceinline__ void mma16816(float* c, const uint32_t* a, uint32_t b0, uint32_t b1) {
    asm volatile("mma.sync.aligned.m16n8k16.row.col.f32.f16.f16.f32 "
                 "{%0,%1,%2,%3}, {%4,%5,%6,%7}, {%8,%9}, {%0,%1,%2,%3};"
                 : "+f"(c[0]), "+f"(c[1]), "+f"(c[2]), "+f"(c[3])
                 : "r"(a[0]), "r"(a[1]), "r"(a[2]), "r"(a[3]), "r"(b0), "r"(b1));
}
__device__ __forceinline__ uint32_t packh2(float lo, float hi) {
    uint32_t r;
    asm("cvt.rn.f16x2.f32 %0, %1, %2;" : "=r"(r) : "f"(hi), "f"(lo));
    return r;
}
__device__ __forceinline__ float fexp2f(float t) {
    t = fmaxf(t, -126.0f);
    const float r = t + 12582912.0f;
    const float f = t - (r - 12582912.0f);
    const int   n = __float_as_int(r) - 0x4B400000;
    float p =        1.3333558146428443e-3f;
    p = fmaf(p, f,   9.6181291076284771e-3f);
    p = fmaf(p, f,   5.5504108664821580e-2f);
    p = fmaf(p, f,   2.4022650695910071e-1f);
    p = fmaf(p, f,   6.9314718055994531e-1f);
    p = fmaf(p, f,   1.0f);
    return __int_as_float(__float_as_int(p) + (n << 23));
}

// ---------------------------------------------------------------------------
__global__ void f2h(const float* __restrict__ src, __half* __restrict__ dst, int n4) {
    const int i = blockIdx.x * blockDim.x + threadIdx.x;
    if (i < n4) {
        const float4 v = ((const float4*)src)[i];
        ((uint32_t*)dst)[2 * i + 0] = packh2(v.x, v.y);
        ((uint32_t*)dst)[2 * i + 1] = packh2(v.z, v.w);
    }
}

// ---------------------------------------------------------------------------
// C[m,n] = sum_k A[m,k] W[n,k] + bias[n].  A,W fp16 row-major [.,1024].
// Tile 128x128, Kstage=64 halves (128B rows, xor-swizzled), 8 warps (4m x 2n),
// warp tile 32x64, cp.async double buffer. OUT: 0 = fp16 head layout, 1 = fp32.
// ---------------------------------------------------------------------------
template<int OUT>
__global__ void __launch_bounds__(256)
gemm_hmma(const __half* __restrict__ A, const __half* __restrict__ W,
          const float* __restrict__ bias, void* __restrict__ Cout)
{
    extern __shared__ char smem[];
    const uint32_t sb = smem_u32(smem);                 // [stage][A 16K | B 16K]
    const int tid = threadIdx.x, wid = tid >> 5, lane = tid & 31;
    const int m0 = blockIdx.y << 7, n0 = blockIdx.x << 7;
    const int wm = (wid & 3) << 5, wn = (wid >> 2) << 6;

    float acc[2][8][4];
#pragma unroll
    for (int mt = 0; mt < 2; mt++)
#pragma unroll
        for (int nt = 0; nt < 8; nt++)
#pragma unroll
            for (int c = 0; c < 4; c++) acc[mt][nt][c] = 0.f;

    auto load_stage = [&](int s, int buf) {
        const uint32_t sA = sb + buf * 32768, sB = sA + 16384;
        const __half* ga = A + (size_t)m0 * 1024 + s * 64;
        const __half* gb = W + (size_t)n0 * 1024 + s * 64;
#pragma unroll
        for (int i = 0; i < 4; i++) {
            const int id = tid + (i << 8), r = id >> 3, c = id & 7;
            CP16(sA + r * 128 + ((c * 16) ^ ((r & 7) << 4)), ga + (size_t)r * 1024 + c * 8);
        }
#pragma unroll
        for (int i = 0; i < 4; i++) {
            const int id = tid + (i << 8), r = id >> 3, c = id & 7;
            CP16(sB + r * 128 + ((c * 16) ^ ((r & 7) << 4)), gb + (size_t)r * 1024 + c * 8);
        }
    };

    load_stage(0, 0); CP_COMMIT();
    load_stage(1, 1); CP_COMMIT();

    for (int s = 0; s < 16; s++) {
        if (s < 15) CP_WAIT1(); else CP_WAIT0();
        __syncthreads();
        const uint32_t sA = sb + (s & 1) * 32768, sB = sA + 16384;
#pragma unroll
        for (int kd = 0; kd < 4; kd++) {
            uint32_t a[2][4];
#pragma unroll
            for (int mt = 0; mt < 2; mt++) {
                const int r = wm + mt * 16 + (lane & 15);
                const int cb = kd * 32 + ((lane >> 4) << 4);
                ldsm4(a[mt][0], a[mt][1], a[mt][2], a[mt][3],
                      sA + r * 128 + (cb ^ ((r & 7) << 4)));
            }
#pragma unroll
            for (int nt2 = 0; nt2 < 4; nt2++) {
                uint32_t b[4];
                const int r = wn + nt2 * 16 + ((lane >> 4) << 3) + (lane & 7);
                const int cb = kd * 32 + (((lane >> 3) & 1) << 4);
                ldsm4(b[0], b[1], b[2], b[3], sB + r * 128 + (cb ^ ((r & 7) << 4)));
#pragma unroll
                for (int mt = 0; mt < 2; mt++) {
                    mma16816(acc[mt][nt2 * 2 + 0], a[mt], b[0], b[1]);
                    mma16816(acc[mt][nt2 * 2 + 1], a[mt], b[2], b[3]);
                }
            }
        }
        __syncthreads();
        if (s + 2 < 16) { load_stage(s + 2, s & 1); CP_COMMIT(); }
    }

    const int r0 = lane >> 2, colq = (lane & 3) * 2;
#pragma unroll
    for (int mt = 0; mt < 2; mt++) {
        const int row0 = m0 + wm + mt * 16 + r0;
#pragma unroll
        for (int nt = 0; nt < 8; nt++) {
            const int col = n0 + wn + nt * 8 + colq;
            const float2 bv = *(const float2*)(bias + col);
            const float v0 = acc[mt][nt][0] + bv.x, v1 = acc[mt][nt][1] + bv.y;
            const float v2 = acc[mt][nt][2] + bv.x, v3 = acc[mt][nt][3] + bv.y;
            if (OUT == 0) {
                __half* C = (__half*)Cout;
                const int b = row0 >> 11, h = col >> 6, d = col & 63;
                const size_t hb = (size_t)(((b << 4) + h) << 11);
                *(uint32_t*)(C + (hb + (row0 & 2047)) * 64 + d)       = packh2(v0, v1);
                *(uint32_t*)(C + (hb + ((row0 + 8) & 2047)) * 64 + d) = packh2(v2, v3);
            } else {
                float* C = (float*)Cout;
                *(float2*)(C + (size_t)row0 * 1024 + col)       = make_float2(v0, v1);
                *(float2*)(C + (size_t)(row0 + 8) * 1024 + col) = make_float2(v2, v3);
            }
        }
    }
}

// ---------------------------------------------------------------------------
// Flash attention, fp16 HMMA. Block = (128 queries, bh). 8 warps x 16 rows.
// KV tiles of 128 keys, cp.async double-buffered. P reused from S fragments.
// ---------------------------------------------------------------------------
__global__ void __launch_bounds__(256)
flash_hmma(const __half* __restrict__ Q, const __half* __restrict__ K,
           const __half* __restrict__ V, __half* __restrict__ O)
{
    extern __shared__ char smem[];
    const uint32_t sb = smem_u32(smem);
    const uint32_t sQ = sb, sK = sb + 16384, sV = sb + 3 * 16384;   // K,V double-buffered
    const int tid = threadIdx.x, wid = tid >> 5, lane = tid & 31;
    const int q0 = blockIdx.x << 7, bh = blockIdx.y;
    const size_t base = (size_t)bh * (2048 * 64);
    const __half* Qb = Q + base + (size_t)q0 * 64;
    const __half* Kb = K + base;
    const __half* Vb = V + base;

#pragma unroll
    for (int i = 0; i < 4; i++) {                       // Q tile: 128 x 64 halves
        const int id = tid + (i << 8), r = id >> 3, c = id & 7;
        CP16(sQ + r * 128 + ((c * 16) ^ ((r & 7) << 4)), Qb + (size_t)r * 64 + c * 8);
    }
    auto load_kv = [&](int t, int buf) {
        const __half* kg = Kb + (size_t)(t << 7) * 64;
        const __half* vg = Vb + (size_t)(t << 7) * 64;
        const uint32_t ks_ = sK + buf * 16384, vs_ = sV + buf * 16384;
#pragma unroll
        for (int i = 0; i < 4; i++) {
            const int id = tid + (i << 8), r = id >> 3, c = id & 7;
            const uint32_t off = r * 128 + ((c * 16) ^ ((r & 7) << 4));
            CP16(ks_ + off, kg + (size_t)r * 64 + c * 8);
        }
#pragma unroll
        for (int i = 0; i < 4; i++) {
            const int id = tid + (i << 8), r = id >> 3, c = id & 7;
            const uint32_t off = r * 128 + ((c * 16) ^ ((r & 7) << 4));
            CP16(vs_ + off, vg + (size_t)r * 64 + c * 8);
        }
    };
    load_kv(0, 0); CP_COMMIT();
    CP_WAIT0();
    __syncthreads();

    uint32_t qf[4][4];                                  // Q fragments, whole block
#pragma unroll
    for (int kd = 0; kd < 4; kd++) {
        const int r = (wid << 4) + (lane & 15);
        const int cb = kd * 32 + ((lane >> 4) << 4);
        ldsm4(qf[kd][0], qf[kd][1], qf[kd][2], qf[kd][3], sQ + r * 128 + (cb ^ ((r & 7) << 4)));
    }

    float oacc[8][4];
#pragma unroll
    for (int dn = 0; dn < 8; dn++)
#pragma unroll
        for (int c = 0; c < 4; c++) oacc[dn][c] = 0.f;
    float m0r = -3.0e38f, m1r = -3.0e38f, l0 = 0.f, l1 = 0.f;

    for (int t = 0; t < 16; t++) {
        if (t < 15) load_kv(t + 1, (t + 1) & 1);
        CP_COMMIT();
        if (t < 15) CP_WAIT1(); else CP_WAIT0();
        __syncthreads();
        const uint32_t ks_ = sK + (t & 1) * 16384, vs_ = sV + (t & 1) * 16384;

        // S = Q K^T
        float sacc[16][4];
#pragma unroll
        for (int nt = 0; nt < 16; nt++)
#pragma unroll
            for (int c = 0; c < 4; c++) sacc[nt][c] = 0.f;
#pragma unroll
        for (int kd = 0; kd < 4; kd++) {
#pragma unroll
            for (int nt2 = 0; nt2 < 8; nt2++) {
                uint32_t b[4];
                const int r = nt2 * 16 + ((lane >> 4) << 3) + (lane & 7);
                const int cb = kd * 32 + (((lane >> 3) & 1) << 4);
                ldsm4(b[0], b[1], b[2], b[3], ks_ + r * 128 + (cb ^ ((r & 7) << 4)));
                mma16816(sacc[nt2 * 2 + 0], qf[kd], b[0], b[1]);
                mma16816(sacc[nt2 * 2 + 1], qf[kd], b[2], b[3]);
            }
        }

        // online softmax (rows r0 = lane>>2 and r0+8; quad lanes share a row)
        float mx0 = sacc[0][0], mx1 = sacc[0][2];
#pragma unroll
        for (int nt = 0; nt < 16; nt++) {
            mx0 = fmaxf(mx0, fmaxf(sacc[nt][0], sacc[nt][1]));
            mx1 = fmaxf(mx1, fmaxf(sacc[nt][2], sacc[nt][3]));
        }
        mx0 = fmaxf(mx0, __shfl_xor_sync(0xffffffffu, mx0, 1));
        mx0 = fmaxf(mx0, __shfl_xor_sync(0xffffffffu, mx0, 2));
        mx1 = fmaxf(mx1, __shfl_xor_sync(0xffffffffu, mx1, 1));
        mx1 = fmaxf(mx1, __shfl_xor_sync(0xffffffffu, mx1, 2));
        const float mn0 = fmaxf(m0r, mx0), mn1 = fmaxf(m1r, mx1);
        const float al0 = fexp2f((m0r - mn0) * CEXP);
        const float al1 = fexp2f((m1r - mn1) * CEXP);
        m0r = mn0; m1r = mn1;
#pragma unroll
        for (int dn = 0; dn < 8; dn++) {
            oacc[dn][0] *= al0; oacc[dn][1] *= al0;
            oacc[dn][2] *= al1; oacc[dn][3] *= al1;
        }
        float s0 = 0.f, s1 = 0.f;
        uint32_t pa[16][2];
#pragma unroll
        for (int nt = 0; nt < 16; nt++) {
            const float p0 = fexp2f((sacc[nt][0] - mn0) * CEXP);
            const float p1 = fexp2f((sacc[nt][1] - mn0) * CEXP);
            const float p2 = fexp2f((sacc[nt][2] - mn1) * CEXP);
            const float p3 = fexp2f((sacc[nt][3] - mn1) * CEXP);
            s0 += p0 + p1; s1 += p2 + p3;
            pa[nt][0] = packh2(p0, p1);
            pa[nt][1] = packh2(p2, p3);
        }
        s0 += __shfl_xor_sync(0xffffffffu, s0, 1);
        s0 += __shfl_xor_sync(0xffffffffu, s0, 2);
        s1 += __shfl_xor_sync(0xffffffffu, s1, 1);
        s1 += __shfl_xor_sync(0xffffffffu, s1, 2);
        l0 = l0 * al0 + s0;
        l1 = l1 * al1 + s1;

        // O += P V   (P = A fragments straight from S c-fragments)
#pragma unroll
        for (int ks = 0; ks < 8; ks++) {
            const uint32_t a[4] = {pa[2 * ks][0], pa[2 * ks][1],
                                   pa[2 * ks + 1][0], pa[2 * ks + 1][1]};
#pragma unroll
            for (int dn2 = 0; dn2 < 4; dn2++) {
                uint32_t b[4];
                const int r = ks * 16 + (lane & 15);
                const int cb = dn2 * 32 + ((lane >> 4) << 4);
                ldsm4t(b[0], b[1], b[2], b[3], vs_ + r * 128 + (cb ^ ((r & 7) << 4)));
                mma16816(oacc[dn2 * 2 + 0], a, b[0], b[1]);
                mma16816(oacc[dn2 * 2 + 1], a, b[2], b[3]);
            }
        }
        __syncthreads();
    }

    // normalize + write packed [b][s][h*64+d] fp16
    const int b_ = bh >> 4, h_ = bh & 15;
    __half* Ob = O + ((size_t)b_ * 2048 + q0) * 1024 + h_ * 64;
    const float inv0 = 1.f / l0, inv1 = 1.f / l1;
    const int r0 = (wid << 4) + (lane >> 2), colq = (lane & 3) * 2;
#pragma unroll
    for (int dn = 0; dn < 8; dn++) {
        const int col = dn * 8 + colq;
        *(uint32_t*)(Ob + (size_t)r0 * 1024 + col) =
            packh2(oacc[dn][0] * inv0, oacc[dn][1] * inv0);
        *(uint32_t*)(Ob + (size_t)(r0 + 8) * 1024 + col) =
            packh2(oacc[dn][2] * inv1, oacc[dn][3] * inv1);
    }
}

// ---------------------------------------------------------------------------
extern "C" void kernel_launch(void* const* d_in, const int* in_sizes, int n_in,
                              void* d_out, int out_size)
{
    const float* x  = (const float*)d_in[0];
    const float* wq = (const float*)d_in[1];
    const float* bq = (const float*)d_in[2];
    const float* wk = (const float*)d_in[3];
    const float* bk = (const float*)d_in[4];
    const float* wv = (const float*)d_in[5];
    const float* bv = (const float*)d_in[6];
    const float* wo = (const float*)d_in[7];
    const float* bo = (const float*)d_in[8];
    float* out = (float*)d_out;

    __half *xh, *wh, *qh, *kh, *vh, *aoh;
    cudaGetSymbolAddress((void**)&xh,  g_xh);
    cudaGetSymbolAddress((void**)&wh,  g_wh);
    cudaGetSymbolAddress((void**)&qh,  g_qh);
    cudaGetSymbolAddress((void**)&kh,  g_kh);
    cudaGetSymbolAddress((void**)&vh,  g_vh);
    cudaGetSymbolAddress((void**)&aoh, g_aoh);

    const int GEMM_SMEM = 65536, FLASH_SMEM = 81920;
    cudaFuncSetAttribute(gemm_hmma<0>, cudaFuncAttributeMaxDynamicSharedMemorySize, GEMM_SMEM);
    cudaFuncSetAttribute(gemm_hmma<1>, cudaFuncAttributeMaxDynamicSharedMemorySize, GEMM_SMEM);
    cudaFuncSetAttribute(flash_hmma, cudaFuncAttributeMaxDynamicSharedMemorySize, FLASH_SMEM);

    f2h<<<8192, 256>>>(x,  xh, 2097152);
    f2h<<<1024, 256>>>(wq, wh + 0,       262144);
    f2h<<<1024, 256>>>(wk, wh + 1048576, 262144);
    f2h<<<1024, 256>>>(wv, wh + 2097152, 262144);
    f2h<<<1024, 256>>>(wo, wh + 3145728, 262144);

    const dim3 gg(8, 64);
    gemm_hmma<0><<<gg, 256, GEMM_SMEM>>>(xh, wh + 0,       bq, qh);
    gemm_hmma<0><<<gg, 256, GEMM_SMEM>>>(xh, wh + 1048576, bk, kh);
    gemm_hmma<0><<<gg, 256, GEMM_SMEM>>>(xh, wh + 2097152, bv, vh);
    flash_hmma<<<dim3(16, 64), 256, FLASH_SMEM>>>(qh, kh, vh, aoh);
    gemm_hmma<1><<<gg, 256, GEMM_SMEM>>>(aoh, wh + 3145728, bo, out);
}

// round 4
// speedup vs baseline: 7.6434x; 1.2651x over previous
#include <cuda_runtime.h>
#include <cuda_fp16.h>
#include <cstdint>

#define CEXP 0.18033688011112042f   // 0.125 * log2(e), folded into Q projection

// fp16 scratch
static __device__ __align__(16) __half g_xh[8388608];   // x as fp16
static __device__ __align__(16) __half g_wh[4194304];   // wq|wk|wv|wo as fp16
static __device__ __align__(16) __half g_qh[8388608];   // [b][h][s][d], pre-scaled by CEXP
static __device__ __align__(16) __half g_kh[8388608];
static __device__ __align__(16) __half g_vh[8388608];
static __device__ __align__(16) __half g_aoh[8388608];  // [b][s][h*d]

// ---------------------------------------------------------------------------
__device__ __forceinline__ uint32_t smem_u32(const void* p) {
    uint32_t a;
    asm("{ .reg .u64 t; cvta.to.shared.u64 t, %1; cvt.u32.u64 %0, t; }" : "=r"(a) : "l"(p));
    return a;
}
#define CP16(s, g) asm volatile("cp.async.cg.shared.global [%0], [%1], 16;" :: "r"(s), "l"(g))
#define CP_COMMIT() asm volatile("cp.async.commit_group;" ::: "memory")
#define CP_WAIT0()  asm volatile("cp.async.wait_group 0;" ::: "memory")
#define CP_WAIT1()  asm volatile("cp.async.wait_group 1;" ::: "memory")

__device__ __forceinline__ void ldsm4(uint32_t& r0, uint32_t& r1, uint32_t& r2, uint32_t& r3,
                                      uint32_t a) {
    asm volatile("ldmatrix.sync.aligned.m8n8.x4.shared.b16 {%0,%1,%2,%3}, [%4];"
                 : "=r"(r0), "=r"(r1), "=r"(r2), "=r"(r3) : "r"(a));
}
__device__ __forceinline__ void ldsm4t(uint32_t& r0, uint32_t& r1, uint32_t& r2, uint32_t& r3,
                                       uint32_t a) {
    asm volatile("ldmatrix.sync.aligned.m8n8.x4.trans.shared.b16 {%0,%1,%2,%3}, [%4];"
                 : "=r"(r0), "=r"(r1), "=r"(r2), "=r"(r3) : "r"(a));
}
__device__ __forceinline__ void mma16816(float* c, const uint32_t* a, uint32_t b0, uint32_t b1) {
    asm volatile("mma.sync.aligned.m16n8k16.row.col.f32.f16.f16.f32 "
                 "{%0,%1,%2,%3}, {%4,%5,%6,%7}, {%8,%9}, {%0,%1,%2,%3};"
                 : "+f"(c[0]), "+f"(c[1]), "+f"(c[2]), "+f"(c[3])
                 : "r"(a[0]), "r"(a[1]), "r"(a[2]), "r"(a[3]), "r"(b0), "r"(b1));
}
__device__ __forceinline__ uint32_t packh2(float lo, float hi) {
    uint32_t r;
    asm("cvt.rn.f16x2.f32 %0, %1, %2;" : "=r"(r) : "f"(hi), "f"(lo));
    return r;
}
// MUFU-based 2^x (idle pipe; rel err ~2^-21)
__device__ __forceinline__ float ex2f(float x) {
    float r;
    asm("ex2.approx.f32 %0, %1;" : "=f"(r) : "f"(x));
    return r;
}

// ---------------------------------------------------------------------------
__global__ void f2h(const float* __restrict__ src, __half* __restrict__ dst, int n4) {
    const int i = blockIdx.x * blockDim.x + threadIdx.x;
    if (i < n4) {
        const float4 v = ((const float4*)src)[i];
        ((uint32_t*)dst)[2 * i + 0] = packh2(v.x, v.y);
        ((uint32_t*)dst)[2 * i + 1] = packh2(v.z, v.w);
    }
}
__global__ void f2h4(const float* __restrict__ s0, const float* __restrict__ s1,
                     const float* __restrict__ s2, const float* __restrict__ s3,
                     __half* __restrict__ dst) {
    const int i = blockIdx.x * blockDim.x + threadIdx.x;   // 0..262143
    const float* src = (blockIdx.y == 0) ? s0 : (blockIdx.y == 1) ? s1
                      : (blockIdx.y == 2) ? s2 : s3;
    const float4 v = ((const float4*)src)[i];
    uint32_t* d = (uint32_t*)(dst + (size_t)blockIdx.y * 1048576);
    d[2 * i + 0] = packh2(v.x, v.y);
    d[2 * i + 1] = packh2(v.z, v.w);
}

// ---------------------------------------------------------------------------
// C[m,n] = (sum_k A[m,k] W[n,k] + bias[n]) * scale.  A,W fp16 row-major [.,1024].
// Tile 128x128, Kstage=64 halves, 8 warps (4m x 2n), cp.async double buffer.
// OUT: 0 = fp16 head layout, 1 = fp32 row-major.
// ---------------------------------------------------------------------------
template<int OUT>
__global__ void __launch_bounds__(256, 2)
gemm_hmma(const __half* __restrict__ A, const __half* __restrict__ W,
          const float* __restrict__ bias, void* __restrict__ Cout, float scale)
{
    extern __shared__ char smem[];
    const uint32_t sb = smem_u32(smem);                 // [stage][A 16K | B 16K]
    const int tid = threadIdx.x, wid = tid >> 5, lane = tid & 31;
    const int m0 = blockIdx.y << 7, n0 = blockIdx.x << 7;
    const int wm = (wid & 3) << 5, wn = (wid >> 2) << 6;

    float acc[2][8][4];
#pragma unroll
    for (int mt = 0; mt < 2; mt++)
#pragma unroll
        for (int nt = 0; nt < 8; nt++)
#pragma unroll
            for (int c = 0; c < 4; c++) acc[mt][nt][c] = 0.f;

    auto load_stage = [&](int s, int buf) {
        const uint32_t sA = sb + buf * 32768, sB = sA + 16384;
        const __half* ga = A + (size_t)m0 * 1024 + s * 64;
        const __half* gb = W + (size_t)n0 * 1024 + s * 64;
#pragma unroll
        for (int i = 0; i < 4; i++) {
            const int id = tid + (i << 8), r = id >> 3, c = id & 7;
            CP16(sA + r * 128 + ((c * 16) ^ ((r & 7) << 4)), ga + (size_t)r * 1024 + c * 8);
        }
#pragma unroll
        for (int i = 0; i < 4; i++) {
            const int id = tid + (i << 8), r = id >> 3, c = id & 7;
            CP16(sB + r * 128 + ((c * 16) ^ ((r & 7) << 4)), gb + (size_t)r * 1024 + c * 8);
        }
    };

    load_stage(0, 0); CP_COMMIT();
    load_stage(1, 1); CP_COMMIT();

    for (int s = 0; s < 16; s++) {
        if (s < 15) CP_WAIT1(); else CP_WAIT0();
        __syncthreads();
        const uint32_t sA = sb + (s & 1) * 32768, sB = sA + 16384;
#pragma unroll
        for (int kd = 0; kd < 4; kd++) {
            uint32_t a[2][4];
#pragma unroll
            for (int mt = 0; mt < 2; mt++) {
                const int r = wm + mt * 16 + (lane & 15);
                const int cb = kd * 32 + ((lane >> 4) << 4);
                ldsm4(a[mt][0], a[mt][1], a[mt][2], a[mt][3],
                      sA + r * 128 + (cb ^ ((r & 7) << 4)));
            }
#pragma unroll
            for (int nt2 = 0; nt2 < 4; nt2++) {
                uint32_t b[4];
                const int r = wn + nt2 * 16 + ((lane >> 4) << 3) + (lane & 7);
                const int cb = kd * 32 + (((lane >> 3) & 1) << 4);
                ldsm4(b[0], b[1], b[2], b[3], sB + r * 128 + (cb ^ ((r & 7) << 4)));
#pragma unroll
                for (int mt = 0; mt < 2; mt++) {
                    mma16816(acc[mt][nt2 * 2 + 0], a[mt], b[0], b[1]);
                    mma16816(acc[mt][nt2 * 2 + 1], a[mt], b[2], b[3]);
                }
            }
        }
        __syncthreads();
        if (s + 2 < 16) { load_stage(s + 2, s & 1); CP_COMMIT(); }
    }

    const int r0 = lane >> 2, colq = (lane & 3) * 2;
#pragma unroll
    for (int mt = 0; mt < 2; mt++) {
        const int row0 = m0 + wm + mt * 16 + r0;
#pragma unroll
        for (int nt = 0; nt < 8; nt++) {
            const int col = n0 + wn + nt * 8 + colq;
            const float2 bv = *(const float2*)(bias + col);
            const float v0 = (acc[mt][nt][0] + bv.x) * scale;
            const float v1 = (acc[mt][nt][1] + bv.y) * scale;
            const float v2 = (acc[mt][nt][2] + bv.x) * scale;
            const float v3 = (acc[mt][nt][3] + bv.y) * scale;
            if (OUT == 0) {
                __half* C = (__half*)Cout;
                const int b = row0 >> 11, h = col >> 6, d = col & 63;
                const size_t hb = (size_t)(((b << 4) + h) << 11);
                *(uint32_t*)(C + (hb + (row0 & 2047)) * 64 + d)       = packh2(v0, v1);
                *(uint32_t*)(C + (hb + ((row0 + 8) & 2047)) * 64 + d) = packh2(v2, v3);
            } else {
                float* C = (float*)Cout;
                *(float2*)(C + (size_t)row0 * 1024 + col)       = make_float2(v0, v1);
                *(float2*)(C + (size_t)(row0 + 8) * 1024 + col) = make_float2(v2, v3);
            }
        }
    }
}

// ---------------------------------------------------------------------------
// Flash attention, fp16 HMMA. Q pre-scaled by CEXP -> scores already in
// scaled-log2 domain. exp via MUFU ex2.approx; row sums via HMMA w/ ones-B.
// ---------------------------------------------------------------------------
__global__ void __launch_bounds__(256)
flash_hmma(const __half* __restrict__ Q, const __half* __restrict__ K,
           const __half* __restrict__ V, __half* __restrict__ O)
{
    extern __shared__ char smem[];
    const uint32_t sb = smem_u32(smem);
    const uint32_t sQ = sb, sK = sb + 16384, sV = sb + 3 * 16384;   // K,V double-buffered
    const int tid = threadIdx.x, wid = tid >> 5, lane = tid & 31;
    const int q0 = blockIdx.x << 7, bh = blockIdx.y;
    const size_t base = (size_t)bh * (2048 * 64);
    const __half* Qb = Q + base + (size_t)q0 * 64;
    const __half* Kb = K + base;
    const __half* Vb = V + base;
    const uint32_t ONES = 0x3C003C00u;

#pragma unroll
    for (int i = 0; i < 4; i++) {                       // Q tile: 128 x 64 halves
        const int id = tid + (i << 8), r = id >> 3, c = id & 7;
        CP16(sQ + r * 128 + ((c * 16) ^ ((r & 7) << 4)), Qb + (size_t)r * 64 + c * 8);
    }
    auto load_kv = [&](int t, int buf) {
        const __half* kg = Kb + (size_t)(t << 7) * 64;
        const __half* vg = Vb + (size_t)(t << 7) * 64;
        const uint32_t ks_ = sK + buf * 16384, vs_ = sV + buf * 16384;
#pragma unroll
        for (int i = 0; i < 4; i++) {
            const int id = tid + (i << 8), r = id >> 3, c = id & 7;
            const uint32_t off = r * 128 + ((c * 16) ^ ((r & 7) << 4));
            CP16(ks_ + off, kg + (size_t)r * 64 + c * 8);
        }
#pragma unroll
        for (int i = 0; i < 4; i++) {
            const int id = tid + (i << 8), r = id >> 3, c = id & 7;
            const uint32_t off = r * 128 + ((c * 16) ^ ((r & 7) << 4));
            CP16(vs_ + off, vg + (size_t)r * 64 + c * 8);
        }
    };
    load_kv(0, 0); CP_COMMIT();
    CP_WAIT0();
    __syncthreads();

    uint32_t qf[4][4];
#pragma unroll
    for (int kd = 0; kd < 4; kd++) {
        const int r = (wid << 4) + (lane & 15);
        const int cb = kd * 32 + ((lane >> 4) << 4);
        ldsm4(qf[kd][0], qf[kd][1], qf[kd][2], qf[kd][3], sQ + r * 128 + (cb ^ ((r & 7) << 4)));
    }

    float oacc[8][4];
#pragma unroll
    for (int dn = 0; dn < 8; dn++)
#pragma unroll
        for (int c = 0; c < 4; c++) oacc[dn][c] = 0.f;
    float m0r = -1.0e30f, m1r = -1.0e30f, l0 = 0.f, l1 = 0.f;

    for (int t = 0; t < 16; t++) {
        if (t < 15) load_kv(t + 1, (t + 1) & 1);
        CP_COMMIT();
        if (t < 15) CP_WAIT1(); else CP_WAIT0();
        __syncthreads();
        const uint32_t ks_ = sK + (t & 1) * 16384, vs_ = sV + (t & 1) * 16384;

        // S = Q K^T  (already in scaled-log2 domain)
        float sacc[16][4];
#pragma unroll
        for (int nt = 0; nt < 16; nt++)
#pragma unroll
            for (int c = 0; c < 4; c++) sacc[nt][c] = 0.f;
#pragma unroll
        for (int kd = 0; kd < 4; kd++) {
#pragma unroll
            for (int nt2 = 0; nt2 < 8; nt2++) {
                uint32_t b[4];
                const int r = nt2 * 16 + ((lane >> 4) << 3) + (lane & 7);
                const int cb = kd * 32 + (((lane >> 3) & 1) << 4);
                ldsm4(b[0], b[1], b[2], b[3], ks_ + r * 128 + (cb ^ ((r & 7) << 4)));
                mma16816(sacc[nt2 * 2 + 0], qf[kd], b[0], b[1]);
                mma16816(sacc[nt2 * 2 + 1], qf[kd], b[2], b[3]);
            }
        }

        // online softmax: max pass (quad lanes share each row)
        float mx0 = sacc[0][0], mx1 = sacc[0][2];
#pragma unroll
        for (int nt = 0; nt < 16; nt++) {
            mx0 = fmaxf(mx0, fmaxf(sacc[nt][0], sacc[nt][1]));
            mx1 = fmaxf(mx1, fmaxf(sacc[nt][2], sacc[nt][3]));
        }
        mx0 = fmaxf(mx0, __shfl_xor_sync(0xffffffffu, mx0, 1));
        mx0 = fmaxf(mx0, __shfl_xor_sync(0xffffffffu, mx0, 2));
        mx1 = fmaxf(mx1, __shfl_xor_sync(0xffffffffu, mx1, 1));
        mx1 = fmaxf(mx1, __shfl_xor_sync(0xffffffffu, mx1, 2));
        const float mn0 = fmaxf(m0r, mx0), mn1 = fmaxf(m1r, mx1);
        const float al0 = ex2f(m0r - mn0);
        const float al1 = ex2f(m1r - mn1);
        m0r = mn0; m1r = mn1;
#pragma unroll
        for (int dn = 0; dn < 8; dn++) {
            oacc[dn][0] *= al0; oacc[dn][1] *= al0;
            oacc[dn][2] *= al1; oacc[dn][3] *= al1;
        }
        // exp via MUFU, pack to fp16 fragments
        uint32_t pa[16][2];
#pragma unroll
        for (int nt = 0; nt < 16; nt++) {
            const float p0 = ex2f(sacc[nt][0] - mn0);
            const float p1 = ex2f(sacc[nt][1] - mn0);
            const float p2 = ex2f(sacc[nt][2] - mn1);
            const float p3 = ex2f(sacc[nt][3] - mn1);
            pa[nt][0] = packh2(p0, p1);
            pa[nt][1] = packh2(p2, p3);
        }

        // O += P V ; row sums via extra HMMA with ones-B (no shuffles)
        float rs[4] = {0.f, 0.f, 0.f, 0.f};
#pragma unroll
        for (int ks = 0; ks < 8; ks++) {
            const uint32_t a[4] = {pa[2 * ks][0], pa[2 * ks][1],
                                   pa[2 * ks + 1][0], pa[2 * ks + 1][1]};
            mma16816(rs, a, ONES, ONES);
#pragma unroll
            for (int dn2 = 0; dn2 < 4; dn2++) {
                uint32_t b[4];
                const int r = ks * 16 + (lane & 15);
                const int cb = dn2 * 32 + ((lane >> 4) << 4);
                ldsm4t(b[0], b[1], b[2], b[3], vs_ + r * 128 + (cb ^ ((r & 7) << 4)));
                mma16816(oacc[dn2 * 2 + 0], a, b[0], b[1]);
                mma16816(oacc[dn2 * 2 + 1], a, b[2], b[3]);
            }
        }
        l0 = l0 * al0 + rs[0];
        l1 = l1 * al1 + rs[2];
        __syncthreads();
    }

    // normalize + write packed [b][s][h*64+d] fp16
    const int b_ = bh >> 4, h_ = bh & 15;
    __half* Ob = O + ((size_t)b_ * 2048 + q0) * 1024 + h_ * 64;
    const float inv0 = 1.f / l0, inv1 = 1.f / l1;
    const int r0 = (wid << 4) + (lane >> 2), colq = (lane & 3) * 2;
#pragma unroll
    for (int dn = 0; dn < 8; dn++) {
        const int col = dn * 8 + colq;
        *(uint32_t*)(Ob + (size_t)r0 * 1024 + col) =
            packh2(oacc[dn][0] * inv0, oacc[dn][1] * inv0);
        *(uint32_t*)(Ob + (size_t)(r0 + 8) * 1024 + col) =
            packh2(oacc[dn][2] * inv1, oacc[dn][3] * inv1);
    }
}

// ---------------------------------------------------------------------------
extern "C" void kernel_launch(void* const* d_in, const int* in_sizes, int n_in,
                              void* d_out, int out_size)
{
    const float* x  = (const float*)d_in[0];
    const float* wq = (const float*)d_in[1];
    const float* bq = (const float*)d_in[2];
    const float* wk = (const float*)d_in[3];
    const float* bk = (const float*)d_in[4];
    const float* wv = (const float*)d_in[5];
    const float* bv = (const float*)d_in[6];
    const float* wo = (const float*)d_in[7];
    const float* bo = (const float*)d_in[8];
    float* out = (float*)d_out;

    __half *xh, *wh, *qh, *kh, *vh, *aoh;
    cudaGetSymbolAddress((void**)&xh,  g_xh);
    cudaGetSymbolAddress((void**)&wh,  g_wh);
    cudaGetSymbolAddress((void**)&qh,  g_qh);
    cudaGetSymbolAddress((void**)&kh,  g_kh);
    cudaGetSymbolAddress((void**)&vh,  g_vh);
    cudaGetSymbolAddress((void**)&aoh, g_aoh);

    const int GEMM_SMEM = 65536, FLASH_SMEM = 81920;
    cudaFuncSetAttribute(gemm_hmma<0>, cudaFuncAttributeMaxDynamicSharedMemorySize, GEMM_SMEM);
    cudaFuncSetAttribute(gemm_hmma<1>, cudaFuncAttributeMaxDynamicSharedMemorySize, GEMM_SMEM);
    cudaFuncSetAttribute(flash_hmma, cudaFuncAttributeMaxDynamicSharedMemorySize, FLASH_SMEM);

    f2h<<<8192, 256>>>(x, xh, 2097152);
    f2h4<<<dim3(1024, 4), 256>>>(wq, wk, wv, wo, wh);

    const dim3 gg(8, 64);
    gemm_hmma<0><<<gg, 256, GEMM_SMEM>>>(xh, wh + 0,       bq, qh, CEXP);
    gemm_hmma<0><<<gg, 256, GEMM_SMEM>>>(xh, wh + 1048576, bk, kh, 1.0f);
    gemm_hmma<0><<<gg, 256, GEMM_SMEM>>>(xh, wh + 2097152, bv, vh, 1.0f);
    flash_hmma<<<dim3(16, 64), 256, FLASH_SMEM>>>(qh, kh, vh, aoh);
    gemm_hmma<1><<<gg, 256, GEMM_SMEM>>>(aoh, wh + 3145728, bo, out, 1.0f);
}

// round 5
// speedup vs baseline: 7.7484x; 1.0137x over previous
#include <cuda_runtime.h>
#include <cuda_fp16.h>
#include <cstdint>

#define CEXP 0.18033688011112042f   // 0.125 * log2(e), folded into Q projection

// fp16 scratch
static __device__ __align__(16) __half g_xh[8388608];   // x as fp16
static __device__ __align__(16) __half g_wh[4194304];   // wq|wk|wv|wo as fp16
static __device__ __align__(16) __half g_qh[8388608];   // [b][h][s][d], pre-scaled by CEXP
static __device__ __align__(16) __half g_kh[8388608];
static __device__ __align__(16) __half g_vh[8388608];
static __device__ __align__(16) __half g_aoh[8388608];  // [b][s][h*d]

// ---------------------------------------------------------------------------
__device__ __forceinline__ uint32_t smem_u32(const void* p) {
    uint32_t a;
    asm("{ .reg .u64 t; cvta.to.shared.u64 t, %1; cvt.u32.u64 %0, t; }" : "=r"(a) : "l"(p));
    return a;
}
#define CP16(s, g) asm volatile("cp.async.cg.shared.global [%0], [%1], 16;" :: "r"(s), "l"(g))
#define CP_COMMIT() asm volatile("cp.async.commit_group;" ::: "memory")
#define CP_WAIT0()  asm volatile("cp.async.wait_group 0;" ::: "memory")
#define CP_WAIT1()  asm volatile("cp.async.wait_group 1;" ::: "memory")

__device__ __forceinline__ void ldsm4(uint32_t& r0, uint32_t& r1, uint32_t& r2, uint32_t& r3,
                                      uint32_t a) {
    asm volatile("ldmatrix.sync.aligned.m8n8.x4.shared.b16 {%0,%1,%2,%3}, [%4];"
                 : "=r"(r0), "=r"(r1), "=r"(r2), "=r"(r3) : "r"(a));
}
__device__ __forceinline__ void ldsm4t(uint32_t& r0, uint32_t& r1, uint32_t& r2, uint32_t& r3,
                                       uint32_t a) {
    asm volatile("ldmatrix.sync.aligned.m8n8.x4.trans.shared.b16 {%0,%1,%2,%3}, [%4];"
                 : "=r"(r0), "=r"(r1), "=r"(r2), "=r"(r3) : "r"(a));
}
__device__ __forceinline__ void mma16816(float* c, const uint32_t* a, uint32_t b0, uint32_t b1) {
    asm volatile("mma.sync.aligned.m16n8k16.row.col.f32.f16.f16.f32 "
                 "{%0,%1,%2,%3}, {%4,%5,%6,%7}, {%8,%9}, {%0,%1,%2,%3};"
                 : "+f"(c[0]), "+f"(c[1]), "+f"(c[2]), "+f"(c[3])
                 : "r"(a[0]), "r"(a[1]), "r"(a[2]), "r"(a[3]), "r"(b0), "r"(b1));
}
__device__ __forceinline__ uint32_t packh2(float lo, float hi) {
    uint32_t r;
    asm("cvt.rn.f16x2.f32 %0, %1, %2;" : "=r"(r) : "f"(hi), "f"(lo));
    return r;
}
__device__ __forceinline__ float ex2f(float x) {
    float r;
    asm("ex2.approx.f32 %0, %1;" : "=f"(r) : "f"(x));
    return r;
}

// ---------------------------------------------------------------------------
__global__ void f2h(const float* __restrict__ src, __half* __restrict__ dst, int n4) {
    const int i = blockIdx.x * blockDim.x + threadIdx.x;
    if (i < n4) {
        const float4 v = ((const float4*)src)[i];
        ((uint32_t*)dst)[2 * i + 0] = packh2(v.x, v.y);
        ((uint32_t*)dst)[2 * i + 1] = packh2(v.z, v.w);
    }
}
__global__ void f2h4(const float* __restrict__ s0, const float* __restrict__ s1,
                     const float* __restrict__ s2, const float* __restrict__ s3,
                     __half* __restrict__ dst) {
    const int i = blockIdx.x * blockDim.x + threadIdx.x;   // 0..262143
    const float* src = (blockIdx.y == 0) ? s0 : (blockIdx.y == 1) ? s1
                      : (blockIdx.y == 2) ? s2 : s3;
    const float4 v = ((const float4*)src)[i];
    uint32_t* d = (uint32_t*)(dst + (size_t)blockIdx.y * 1048576);
    d[2 * i + 0] = packh2(v.x, v.y);
    d[2 * i + 1] = packh2(v.z, v.w);
}

// ---------------------------------------------------------------------------
// C[m,n] = (sum_k A[m,k] W[n,k] + bias[n]) * scale.  A,W fp16 row-major [.,1024].
// Tile 128x128, Kstage=64 halves, 3-stage cp.async pipeline, ONE barrier/stage.
// 8 warps (4m x 2n). OUT: 0 = fp16 head layout, 1 = fp32 row-major.
// ---------------------------------------------------------------------------
#define GS 32768                     // bytes per stage (A 16K + B 16K)
#define GEMM_SMEM (3 * GS)

template<int OUT>
__global__ void __launch_bounds__(256, 2)
gemm_hmma(const __half* __restrict__ A, const __half* __restrict__ W,
          const float* __restrict__ bias, void* __restrict__ Cout, float scale)
{
    extern __shared__ char smem[];
    const uint32_t sb = smem_u32(smem);
    const int tid = threadIdx.x, wid = tid >> 5, lane = tid & 31;
    const int m0 = blockIdx.y << 7, n0 = blockIdx.x << 7;
    const int wm = (wid & 3) << 5, wn = (wid >> 2) << 6;

    float acc[2][8][4];
#pragma unroll
    for (int mt = 0; mt < 2; mt++)
#pragma unroll
        for (int nt = 0; nt < 8; nt++)
#pragma unroll
            for (int c = 0; c < 4; c++) acc[mt][nt][c] = 0.f;

    auto load_stage = [&](int s, int buf) {
        const uint32_t sA = sb + buf * GS, sB = sA + 16384;
        const __half* ga = A + (size_t)m0 * 1024 + s * 64;
        const __half* gb = W + (size_t)n0 * 1024 + s * 64;
#pragma unroll
        for (int i = 0; i < 4; i++) {
            const int id = tid + (i << 8), r = id >> 3, c = id & 7;
            CP16(sA + r * 128 + ((c * 16) ^ ((r & 7) << 4)), ga + (size_t)r * 1024 + c * 8);
        }
#pragma unroll
        for (int i = 0; i < 4; i++) {
            const int id = tid + (i << 8), r = id >> 3, c = id & 7;
            CP16(sB + r * 128 + ((c * 16) ^ ((r & 7) << 4)), gb + (size_t)r * 1024 + c * 8);
        }
    };

    load_stage(0, 0); CP_COMMIT();
    load_stage(1, 1); CP_COMMIT();

    int cbuf = 0, lbuf = 2;
    for (int s = 0; s < 16; s++) {
        if (s < 15) CP_WAIT1(); else CP_WAIT0();
        __syncthreads();                      // stage s visible to all; skew <= 1 iter
        const uint32_t sA = sb + cbuf * GS, sB = sA + 16384;
#pragma unroll
        for (int kd = 0; kd < 4; kd++) {
            uint32_t a[2][4];
#pragma unroll
            for (int mt = 0; mt < 2; mt++) {
                const int r = wm + mt * 16 + (lane & 15);
                const int cb = kd * 32 + ((lane >> 4) << 4);
                ldsm4(a[mt][0], a[mt][1], a[mt][2], a[mt][3],
                      sA + r * 128 + (cb ^ ((r & 7) << 4)));
            }
#pragma unroll
            for (int nt2 = 0; nt2 < 4; nt2++) {
                uint32_t b[4];
                const int r = wn + nt2 * 16 + ((lane >> 4) << 3) + (lane & 7);
                const int cb = kd * 32 + (((lane >> 3) & 1) << 4);
                ldsm4(b[0], b[1], b[2], b[3], sB + r * 128 + (cb ^ ((r & 7) << 4)));
#pragma unroll
                for (int mt = 0; mt < 2; mt++) {
                    mma16816(acc[mt][nt2 * 2 + 0], a[mt], b[0], b[1]);
                    mma16816(acc[mt][nt2 * 2 + 1], a[mt], b[2], b[3]);
                }
            }
        }
        if (s + 2 < 16) { load_stage(s + 2, lbuf); CP_COMMIT(); }
        cbuf = (cbuf == 2) ? 0 : cbuf + 1;
        lbuf = (lbuf == 2) ? 0 : lbuf + 1;
    }

    const int r0 = lane >> 2, colq = (lane & 3) * 2;
#pragma unroll
    for (int mt = 0; mt < 2; mt++) {
        const int row0 = m0 + wm + mt * 16 + r0;
#pragma unroll
        for (int nt = 0; nt < 8; nt++) {
            const int col = n0 + wn + nt * 8 + colq;
            const float2 bv = *(const float2*)(bias + col);
            const float v0 = (acc[mt][nt][0] + bv.x) * scale;
            const float v1 = (acc[mt][nt][1] + bv.y) * scale;
            const float v2 = (acc[mt][nt][2] + bv.x) * scale;
            const float v3 = (acc[mt][nt][3] + bv.y) * scale;
            if (OUT == 0) {
                __half* C = (__half*)Cout;
                const int b = row0 >> 11, h = col >> 6, d = col & 63;
                const size_t hb = (size_t)(((b << 4) + h) << 11);
                *(uint32_t*)(C + (hb + (row0 & 2047)) * 64 + d)       = packh2(v0, v1);
                *(uint32_t*)(C + (hb + ((row0 + 8) & 2047)) * 64 + d) = packh2(v2, v3);
            } else {
                float* C = (float*)Cout;
                *(float2*)(C + (size_t)row0 * 1024 + col)       = make_float2(v0, v1);
                *(float2*)(C + (size_t)(row0 + 8) * 1024 + col) = make_float2(v2, v3);
            }
        }
    }
}

// ---------------------------------------------------------------------------
// Flash attention, fp16 HMMA, 3-stage KV pipeline, ONE barrier per KV tile.
// Q pre-scaled by CEXP; exp via MUFU ex2; row sums via HMMA with ones-B.
// ---------------------------------------------------------------------------
#define FS 32768                     // bytes per KV stage (K 16K + V 16K)
#define FLASH_SMEM (16384 + 3 * FS)

__global__ void __launch_bounds__(256)
flash_hmma(const __half* __restrict__ Q, const __half* __restrict__ K,
           const __half* __restrict__ V, __half* __restrict__ O)
{
    extern __shared__ char smem[];
    const uint32_t sb = smem_u32(smem);
    const uint32_t sQ = sb, sKV = sb + 16384;       // 3 stages of [K 16K | V 16K]
    const int tid = threadIdx.x, wid = tid >> 5, lane = tid & 31;
    const int q0 = blockIdx.x << 7, bh = blockIdx.y;
    const size_t base = (size_t)bh * (2048 * 64);
    const __half* Qb = Q + base + (size_t)q0 * 64;
    const __half* Kb = K + base;
    const __half* Vb = V + base;
    const uint32_t ONES = 0x3C003C00u;

#pragma unroll
    for (int i = 0; i < 4; i++) {                   // Q tile: 128 x 64 halves
        const int id = tid + (i << 8), r = id >> 3, c = id & 7;
        CP16(sQ + r * 128 + ((c * 16) ^ ((r & 7) << 4)), Qb + (size_t)r * 64 + c * 8);
    }
    auto load_kv = [&](int t, int buf) {
        const __half* kg = Kb + (size_t)(t << 7) * 64;
        const __half* vg = Vb + (size_t)(t << 7) * 64;
        const uint32_t ks_ = sKV + buf * FS, vs_ = ks_ + 16384;
#pragma unroll
        for (int i = 0; i < 4; i++) {
            const int id = tid + (i << 8), r = id >> 3, c = id & 7;
            const uint32_t off = r * 128 + ((c * 16) ^ ((r & 7) << 4));
            CP16(ks_ + off, kg + (size_t)r * 64 + c * 8);
        }
#pragma unroll
        for (int i = 0; i < 4; i++) {
            const int id = tid + (i << 8), r = id >> 3, c = id & 7;
            const uint32_t off = r * 128 + ((c * 16) ^ ((r & 7) << 4));
            CP16(vs_ + off, vg + (size_t)r * 64 + c * 8);
        }
    };
    // prologue: Q + stage0 in group0, stage1 in group1
    load_kv(0, 0); CP_COMMIT();
    load_kv(1, 1); CP_COMMIT();
    CP_WAIT1();                                     // Q + stage0 ready
    __syncthreads();

    uint32_t qf[4][4];
#pragma unroll
    for (int kd = 0; kd < 4; kd++) {
        const int r = (wid << 4) + (lane & 15);
        const int cb = kd * 32 + ((lane >> 4) << 4);
        ldsm4(qf[kd][0], qf[kd][1], qf[kd][2], qf[kd][3], sQ + r * 128 + (cb ^ ((r & 7) << 4)));
    }

    float oacc[8][4];
#pragma unroll
    for (int dn = 0; dn < 8; dn++)
#pragma unroll
        for (int c = 0; c < 4; c++) oacc[dn][c] = 0.f;
    float m0r = -1.0e30f, m1r = -1.0e30f, l0 = 0.f, l1 = 0.f;

    int cbuf = 0, lbuf = 2;
    for (int t = 0; t < 16; t++) {
        if (t > 0) {                                 // t==0 already waited
            if (t < 15) CP_WAIT1(); else CP_WAIT0();
            __syncthreads();
        }
        const uint32_t ks_ = sKV + cbuf * FS, vs_ = ks_ + 16384;

        // S = Q K^T  (scaled-log2 domain)
        float sacc[16][4];
#pragma unroll
        for (int nt = 0; nt < 16; nt++)
#pragma unroll
            for (int c = 0; c < 4; c++) sacc[nt][c] = 0.f;
#pragma unroll
        for (int kd = 0; kd < 4; kd++) {
#pragma unroll
            for (int nt2 = 0; nt2 < 8; nt2++) {
                uint32_t b[4];
                const int r = nt2 * 16 + ((lane >> 4) << 3) + (lane & 7);
                const int cb = kd * 32 + (((lane >> 3) & 1) << 4);
                ldsm4(b[0], b[1], b[2], b[3], ks_ + r * 128 + (cb ^ ((r & 7) << 4)));
                mma16816(sacc[nt2 * 2 + 0], qf[kd], b[0], b[1]);
                mma16816(sacc[nt2 * 2 + 1], qf[kd], b[2], b[3]);
            }
        }

        // online softmax (quad lanes share each row)
        float mx0 = sacc[0][0], mx1 = sacc[0][2];
#pragma unroll
        for (int nt = 0; nt < 16; nt++) {
            mx0 = fmaxf(mx0, fmaxf(sacc[nt][0], sacc[nt][1]));
            mx1 = fmaxf(mx1, fmaxf(sacc[nt][2], sacc[nt][3]));
        }
        mx0 = fmaxf(mx0, __shfl_xor_sync(0xffffffffu, mx0, 1));
        mx0 = fmaxf(mx0, __shfl_xor_sync(0xffffffffu, mx0, 2));
        mx1 = fmaxf(mx1, __shfl_xor_sync(0xffffffffu, mx1, 1));
        mx1 = fmaxf(mx1, __shfl_xor_sync(0xffffffffu, mx1, 2));
        const float mn0 = fmaxf(m0r, mx0), mn1 = fmaxf(m1r, mx1);
        const float al0 = ex2f(m0r - mn0);
        const float al1 = ex2f(m1r - mn1);
        m0r = mn0; m1r = mn1;
#pragma unroll
        for (int dn = 0; dn < 8; dn++) {
            oacc[dn][0] *= al0; oacc[dn][1] *= al0;
            oacc[dn][2] *= al1; oacc[dn][3] *= al1;
        }
        uint32_t pa[16][2];
#pragma unroll
        for (int nt = 0; nt < 16; nt++) {
            const float p0 = ex2f(sacc[nt][0] - mn0);
            const float p1 = ex2f(sacc[nt][1] - mn0);
            const float p2 = ex2f(sacc[nt][2] - mn1);
            const float p3 = ex2f(sacc[nt][3] - mn1);
            pa[nt][0] = packh2(p0, p1);
            pa[nt][1] = packh2(p2, p3);
        }

        // O += P V ; row sums via HMMA with ones-B
        float rs[4] = {0.f, 0.f, 0.f, 0.f};
#pragma unroll
        for (int ks = 0; ks < 8; ks++) {
            const uint32_t a[4] = {pa[2 * ks][0], pa[2 * ks][1],
                                   pa[2 * ks + 1][0], pa[2 * ks + 1][1]};
            mma16816(rs, a, ONES, ONES);
#pragma unroll
            for (int dn2 = 0; dn2 < 4; dn2++) {
                uint32_t b[4];
                const int r = ks * 16 + (lane & 15);
                const int cb = dn2 * 32 + ((lane >> 4) << 4);
                ldsm4t(b[0], b[1], b[2], b[3], vs_ + r * 128 + (cb ^ ((r & 7) << 4)));
                mma16816(oacc[dn2 * 2 + 0], a, b[0], b[1]);
                mma16816(oacc[dn2 * 2 + 1], a, b[2], b[3]);
            }
        }
        l0 = l0 * al0 + rs[0];
        l1 = l1 * al1 + rs[2];

        if (t + 2 < 16) { load_kv(t + 2, lbuf); }
        CP_COMMIT();
        cbuf = (cbuf == 2) ? 0 : cbuf + 1;
        lbuf = (lbuf == 2) ? 0 : lbuf + 1;
    }

    // normalize + write packed [b][s][h*64+d] fp16
    const int b_ = bh >> 4, h_ = bh & 15;
    __half* Ob = O + ((size_t)b_ * 2048 + q0) * 1024 + h_ * 64;
    const float inv0 = 1.f / l0, inv1 = 1.f / l1;
    const int r0 = (wid << 4) + (lane >> 2), colq = (lane & 3) * 2;
#pragma unroll
    for (int dn = 0; dn < 8; dn++) {
        const int col = dn * 8 + colq;
        *(uint32_t*)(Ob + (size_t)r0 * 1024 + col) =
            packh2(oacc[dn][0] * inv0, oacc[dn][1] * inv0);
        *(uint32_t*)(Ob + (size_t)(r0 + 8) * 1024 + col) =
            packh2(oacc[dn][2] * inv1, oacc[dn][3] * inv1);
    }
}

// ---------------------------------------------------------------------------
extern "C" void kernel_launch(void* const* d_in, const int* in_sizes, int n_in,
                              void* d_out, int out_size)
{
    const float* x  = (const float*)d_in[0];
    const float* wq = (const float*)d_in[1];
    const float* bq = (const float*)d_in[2];
    const float* wk = (const float*)d_in[3];
    const float* bk = (const float*)d_in[4];
    const float* wv = (const float*)d_in[5];
    const float* bv = (const float*)d_in[6];
    const float* wo = (const float*)d_in[7];
    const float* bo = (const float*)d_in[8];
    float* out = (float*)d_out;

    __half *xh, *wh, *qh, *kh, *vh, *aoh;
    cudaGetSymbolAddress((void**)&xh,  g_xh);
    cudaGetSymbolAddress((void**)&wh,  g_wh);
    cudaGetSymbolAddress((void**)&qh,  g_qh);
    cudaGetSymbolAddress((void**)&kh,  g_kh);
    cudaGetSymbolAddress((void**)&vh,  g_vh);
    cudaGetSymbolAddress((void**)&aoh, g_aoh);

    cudaFuncSetAttribute(gemm_hmma<0>, cudaFuncAttributeMaxDynamicSharedMemorySize, GEMM_SMEM);
    cudaFuncSetAttribute(gemm_hmma<1>, cudaFuncAttributeMaxDynamicSharedMemorySize, GEMM_SMEM);
    cudaFuncSetAttribute(flash_hmma, cudaFuncAttributeMaxDynamicSharedMemorySize, FLASH_SMEM);

    f2h<<<8192, 256>>>(x, xh, 2097152);
    f2h4<<<dim3(1024, 4), 256>>>(wq, wk, wv, wo, wh);

    const dim3 gg(8, 64);
    gemm_hmma<0><<<gg, 256, GEMM_SMEM>>>(xh, wh + 0,       bq, qh, CEXP);
    gemm_hmma<0><<<gg, 256, GEMM_SMEM>>>(xh, wh + 1048576, bk, kh, 1.0f);
    gemm_hmma<0><<<gg, 256, GEMM_SMEM>>>(xh, wh + 2097152, bv, vh, 1.0f);
    flash_hmma<<<dim3(16, 64), 256, FLASH_SMEM>>>(qh, kh, vh, aoh);
    gemm_hmma<1><<<gg, 256, GEMM_SMEM>>>(aoh, wh + 3145728, bo, out, 1.0f);
}

// round 6
// speedup vs baseline: 7.9376x; 1.0244x over previous
#include <cuda_runtime.h>
#include <cuda_fp16.h>
#include <cstdint>

#define CEXP 0.18033688011112042f   // 0.125 * log2(e), folded into Q projection

// fp16 scratch
static __device__ __align__(16) __half g_xh[8388608];   // x as fp16
static __device__ __align__(16) __half g_wh[4194304];   // wq|wk|wv|wo as fp16
static __device__ __align__(16) __half g_qh[8388608];   // [b][h][s][d], pre-scaled by CEXP
static __device__ __align__(16) __half g_kh[8388608];
static __device__ __align__(16) __half g_vh[8388608];
static __device__ __align__(16) __half g_aoh[8388608];  // [b][s][h*d]

// ---------------------------------------------------------------------------
__device__ __forceinline__ uint32_t smem_u32(const void* p) {
    uint32_t a;
    asm("{ .reg .u64 t; cvta.to.shared.u64 t, %1; cvt.u32.u64 %0, t; }" : "=r"(a) : "l"(p));
    return a;
}
#define CP16(s, g) asm volatile("cp.async.cg.shared.global [%0], [%1], 16;" :: "r"(s), "l"(g))
#define CP_COMMIT() asm volatile("cp.async.commit_group;" ::: "memory")
#define CP_WAIT0()  asm volatile("cp.async.wait_group 0;" ::: "memory")
#define CP_WAIT1()  asm volatile("cp.async.wait_group 1;" ::: "memory")

__device__ __forceinline__ void ldsm4(uint32_t* r, uint32_t a) {
    asm volatile("ldmatrix.sync.aligned.m8n8.x4.shared.b16 {%0,%1,%2,%3}, [%4];"
                 : "=r"(r[0]), "=r"(r[1]), "=r"(r[2]), "=r"(r[3]) : "r"(a));
}
__device__ __forceinline__ void ldsm4t(uint32_t* r, uint32_t a) {
    asm volatile("ldmatrix.sync.aligned.m8n8.x4.trans.shared.b16 {%0,%1,%2,%3}, [%4];"
                 : "=r"(r[0]), "=r"(r[1]), "=r"(r[2]), "=r"(r[3]) : "r"(a));
}
__device__ __forceinline__ void mma16816(float* c, const uint32_t* a, uint32_t b0, uint32_t b1) {
    asm volatile("mma.sync.aligned.m16n8k16.row.col.f32.f16.f16.f32 "
                 "{%0,%1,%2,%3}, {%4,%5,%6,%7}, {%8,%9}, {%0,%1,%2,%3};"
                 : "+f"(c[0]), "+f"(c[1]), "+f"(c[2]), "+f"(c[3])
                 : "r"(a[0]), "r"(a[1]), "r"(a[2]), "r"(a[3]), "r"(b0), "r"(b1));
}
__device__ __forceinline__ uint32_t packh2(float lo, float hi) {
    uint32_t r;
    asm("cvt.rn.f16x2.f32 %0, %1, %2;" : "=r"(r) : "f"(hi), "f"(lo));
    return r;
}
__device__ __forceinline__ float ex2f(float x) {
    float r;
    asm("ex2.approx.f32 %0, %1;" : "=f"(r) : "f"(x));
    return r;
}

// ---------------------------------------------------------------------------
__global__ void f2h(const float* __restrict__ src, __half* __restrict__ dst, int n4) {
    const int i = blockIdx.x * blockDim.x + threadIdx.x;
    if (i < n4) {
        const float4 v = ((const float4*)src)[i];
        ((uint32_t*)dst)[2 * i + 0] = packh2(v.x, v.y);
        ((uint32_t*)dst)[2 * i + 1] = packh2(v.z, v.w);
    }
}
__global__ void f2h4(const float* __restrict__ s0, const float* __restrict__ s1,
                     const float* __restrict__ s2, const float* __restrict__ s3,
                     __half* __restrict__ dst) {
    const int i = blockIdx.x * blockDim.x + threadIdx.x;   // 0..262143
    const float* src = (blockIdx.y == 0) ? s0 : (blockIdx.y == 1) ? s1
                      : (blockIdx.y == 2) ? s2 : s3;
    const float4 v = ((const float4*)src)[i];
    uint32_t* d = (uint32_t*)(dst + (size_t)blockIdx.y * 1048576);
    d[2 * i + 0] = packh2(v.x, v.y);
    d[2 * i + 1] = packh2(v.z, v.w);
}

// ---------------------------------------------------------------------------
// Shared GEMM mainloop body (device inline): 128x128 tile, 3-stage cp.async,
// one barrier/stage, fragment-prefetch pipelined MMA stream.
// acc[2][8][4]; A rows from wm, B rows from wn.
// ---------------------------------------------------------------------------
#define GS 32768                     // bytes per stage (A 16K + B 16K)
#define GEMM_SMEM (3 * GS)

struct GemmCtx {
    uint32_t sb;
    int tid, wid, lane, wm, wn;
};

__device__ __forceinline__ void gemm_mainloop(
    const GemmCtx& cx, const __half* __restrict__ A, const __half* __restrict__ W,
    int m0, int n0, float acc[2][8][4])
{
    const int tid = cx.tid, lane = cx.lane, wm = cx.wm, wn = cx.wn;
    const uint32_t sb = cx.sb;

    auto load_stage = [&](int s, int buf) {
        const uint32_t sA = sb + buf * GS, sB = sA + 16384;
        const __half* ga = A + (size_t)m0 * 1024 + s * 64;
        const __half* gb = W + (size_t)n0 * 1024 + s * 64;
#pragma unroll
        for (int i = 0; i < 4; i++) {
            const int id = tid + (i << 8), r = id >> 3, c = id & 7;
            CP16(sA + r * 128 + ((c * 16) ^ ((r & 7) << 4)), ga + (size_t)r * 1024 + c * 8);
        }
#pragma unroll
        for (int i = 0; i < 4; i++) {
            const int id = tid + (i << 8), r = id >> 3, c = id & 7;
            CP16(sB + r * 128 + ((c * 16) ^ ((r & 7) << 4)), gb + (size_t)r * 1024 + c * 8);
        }
    };

    load_stage(0, 0); CP_COMMIT();
    load_stage(1, 1); CP_COMMIT();

    int cbuf = 0, lbuf = 2;
    for (int s = 0; s < 16; s++) {
        if (s < 15) CP_WAIT1(); else CP_WAIT0();
        __syncthreads();                       // stage s visible; buffer lbuf free
        if (s + 2 < 16) { load_stage(s + 2, lbuf); CP_COMMIT(); }

        const uint32_t sA = sb + cbuf * GS, sB = sA + 16384;
        auto ldA = [&](uint32_t a[2][4], int kd) {
#pragma unroll
            for (int mt = 0; mt < 2; mt++) {
                const int r = wm + mt * 16 + (lane & 15);
                const int cb = kd * 32 + ((lane >> 4) << 4);
                ldsm4(a[mt], sA + r * 128 + (cb ^ ((r & 7) << 4)));
            }
        };
        auto ldB = [&](uint32_t b[4], int kd, int nt2) {
            const int r = wn + nt2 * 16 + ((lane >> 4) << 3) + (lane & 7);
            const int cb = kd * 32 + (((lane >> 3) & 1) << 4);
            ldsm4(b, sB + r * 128 + (cb ^ ((r & 7) << 4)));
        };

        uint32_t a[2][2][4], b[2][4];
        ldA(a[0], 0);
        ldB(b[0], 0, 0);
#pragma unroll
        for (int step = 0; step < 16; step++) {
            const int kd = step >> 2, nt2 = step & 3;
            const int cb = step & 1, ab = kd & 1;
            if (step < 15) ldB(b[cb ^ 1], (step + 1) >> 2, (step + 1) & 3);
            if (nt2 == 1 && kd < 3) ldA(a[ab ^ 1], kd + 1);
#pragma unroll
            for (int mt = 0; mt < 2; mt++) {
                mma16816(acc[mt][nt2 * 2 + 0], a[ab][mt], b[cb][0], b[cb][1]);
                mma16816(acc[mt][nt2 * 2 + 1], a[ab][mt], b[cb][2], b[cb][3]);
            }
        }
        cbuf = (cbuf == 2) ? 0 : cbuf + 1;
        lbuf = (lbuf == 2) ? 0 : lbuf + 1;
    }
}

// Merged Q/K/V projection: grid.z selects weight/bias/output. fp16 head layout.
__global__ void __launch_bounds__(256, 2)
gemm_qkv(const __half* __restrict__ A, const __half* __restrict__ Wbase,
         const float* __restrict__ bq, const float* __restrict__ bk,
         const float* __restrict__ bv,
         __half* __restrict__ Cq, __half* __restrict__ Ck, __half* __restrict__ Cv)
{
    extern __shared__ char smem[];
    GemmCtx cx;
    cx.sb = smem_u32(smem);
    cx.tid = threadIdx.x; cx.wid = cx.tid >> 5; cx.lane = cx.tid & 31;
    cx.wm = (cx.wid & 3) << 5; cx.wn = (cx.wid >> 2) << 6;
    const int m0 = blockIdx.y << 7, n0 = blockIdx.x << 7;
    const int z = blockIdx.z;
    const __half* W = Wbase + ((size_t)z << 20);
    const float* bias = (z == 0) ? bq : (z == 1) ? bk : bv;
    __half* C = (z == 0) ? Cq : (z == 1) ? Ck : Cv;
    const float scale = (z == 0) ? CEXP : 1.0f;

    float acc[2][8][4];
#pragma unroll
    for (int mt = 0; mt < 2; mt++)
#pragma unroll
        for (int nt = 0; nt < 8; nt++)
#pragma unroll
            for (int c = 0; c < 4; c++) acc[mt][nt][c] = 0.f;

    gemm_mainloop(cx, A, W, m0, n0, acc);

    const int r0 = cx.lane >> 2, colq = (cx.lane & 3) * 2;
#pragma unroll
    for (int mt = 0; mt < 2; mt++) {
        const int row0 = m0 + cx.wm + mt * 16 + r0;
#pragma unroll
        for (int nt = 0; nt < 8; nt++) {
            const int col = n0 + cx.wn + nt * 8 + colq;
            const float2 bvv = *(const float2*)(bias + col);
            const float v0 = (acc[mt][nt][0] + bvv.x) * scale;
            const float v1 = (acc[mt][nt][1] + bvv.y) * scale;
            const float v2 = (acc[mt][nt][2] + bvv.x) * scale;
            const float v3 = (acc[mt][nt][3] + bvv.y) * scale;
            const int b = row0 >> 11, h = col >> 6, d = col & 63;
            const size_t hb = (size_t)(((b << 4) + h) << 11);
            *(uint32_t*)(C + (hb + (row0 & 2047)) * 64 + d)       = packh2(v0, v1);
            *(uint32_t*)(C + (hb + ((row0 + 8) & 2047)) * 64 + d) = packh2(v2, v3);
        }
    }
}

// Output projection: fp32 row-major out.
__global__ void __launch_bounds__(256, 2)
gemm_o(const __half* __restrict__ A, const __half* __restrict__ W,
       const float* __restrict__ bias, float* __restrict__ C)
{
    extern __shared__ char smem[];
    GemmCtx cx;
    cx.sb = smem_u32(smem);
    cx.tid = threadIdx.x; cx.wid = cx.tid >> 5; cx.lane = cx.tid & 31;
    cx.wm = (cx.wid & 3) << 5; cx.wn = (cx.wid >> 2) << 6;
    const int m0 = blockIdx.y << 7, n0 = blockIdx.x << 7;

    float acc[2][8][4];
#pragma unroll
    for (int mt = 0; mt < 2; mt++)
#pragma unroll
        for (int nt = 0; nt < 8; nt++)
#pragma unroll
            for (int c = 0; c < 4; c++) acc[mt][nt][c] = 0.f;

    gemm_mainloop(cx, A, W, m0, n0, acc);

    const int r0 = cx.lane >> 2, colq = (cx.lane & 3) * 2;
#pragma unroll
    for (int mt = 0; mt < 2; mt++) {
        const int row0 = m0 + cx.wm + mt * 16 + r0;
#pragma unroll
        for (int nt = 0; nt < 8; nt++) {
            const int col = n0 + cx.wn + nt * 8 + colq;
            const float2 bvv = *(const float2*)(bias + col);
            *(float2*)(C + (size_t)row0 * 1024 + col) =
                make_float2(acc[mt][nt][0] + bvv.x, acc[mt][nt][1] + bvv.y);
            *(float2*)(C + (size_t)(row0 + 8) * 1024 + col) =
                make_float2(acc[mt][nt][2] + bvv.x, acc[mt][nt][3] + bvv.y);
        }
    }
}

// ---------------------------------------------------------------------------
// Flash attention, fp16 HMMA, 3-stage KV pipeline, one barrier/tile,
// fragment-prefetch pipelined QK^T and PV streams.
// ---------------------------------------------------------------------------
#define FS 32768                     // bytes per KV stage (K 16K + V 16K)
#define FLASH_SMEM (16384 + 3 * FS)

__global__ void __launch_bounds__(256)
flash_hmma(const __half* __restrict__ Q, const __half* __restrict__ K,
           const __half* __restrict__ V, __half* __restrict__ O)
{
    extern __shared__ char smem[];
    const uint32_t sb = smem_u32(smem);
    const uint32_t sQ = sb, sKV = sb + 16384;       // 3 stages of [K 16K | V 16K]
    const int tid = threadIdx.x, wid = tid >> 5, lane = tid & 31;
    const int q0 = blockIdx.x << 7, bh = blockIdx.y;
    const size_t base = (size_t)bh * (2048 * 64);
    const __half* Qb = Q + base + (size_t)q0 * 64;
    const __half* Kb = K + base;
    const __half* Vb = V + base;
    const uint32_t ONES = 0x3C003C00u;

#pragma unroll
    for (int i = 0; i < 4; i++) {                   // Q tile: 128 x 64 halves
        const int id = tid + (i << 8), r = id >> 3, c = id & 7;
        CP16(sQ + r * 128 + ((c * 16) ^ ((r & 7) << 4)), Qb + (size_t)r * 64 + c * 8);
    }
    auto load_kv = [&](int t, int buf) {
        const __half* kg = Kb + (size_t)(t << 7) * 64;
        const __half* vg = Vb + (size_t)(t << 7) * 64;
        const uint32_t ks_ = sKV + buf * FS, vs_ = ks_ + 16384;
#pragma unroll
        for (int i = 0; i < 4; i++) {
            const int id = tid + (i << 8), r = id >> 3, c = id & 7;
            const uint32_t off = r * 128 + ((c * 16) ^ ((r & 7) << 4));
            CP16(ks_ + off, kg + (size_t)r * 64 + c * 8);
        }
#pragma unroll
        for (int i = 0; i < 4; i++) {
            const int id = tid + (i << 8), r = id >> 3, c = id & 7;
            const uint32_t off = r * 128 + ((c * 16) ^ ((r & 7) << 4));
            CP16(vs_ + off, vg + (size_t)r * 64 + c * 8);
        }
    };
    load_kv(0, 0); CP_COMMIT();
    load_kv(1, 1); CP_COMMIT();
    CP_WAIT1();                                     // Q + stage0 ready
    __syncthreads();

    uint32_t qf[4][4];
#pragma unroll
    for (int kd = 0; kd < 4; kd++) {
        const int r = (wid << 4) + (lane & 15);
        const int cb = kd * 32 + ((lane >> 4) << 4);
        ldsm4(qf[kd], sQ + r * 128 + (cb ^ ((r & 7) << 4)));
    }

    float oacc[8][4];
#pragma unroll
    for (int dn = 0; dn < 8; dn++)
#pragma unroll
        for (int c = 0; c < 4; c++) oacc[dn][c] = 0.f;
    float m0r = -1.0e30f, m1r = -1.0e30f, l0 = 0.f, l1 = 0.f;

    int cbuf = 0, lbuf = 2;
    for (int t = 0; t < 16; t++) {
        if (t > 0) {
            if (t < 15) CP_WAIT1(); else CP_WAIT0();
            __syncthreads();
        }
        if (t + 2 < 16) { load_kv(t + 2, lbuf); }   // lbuf free after barrier
        CP_COMMIT();
        const uint32_t ks_ = sKV + cbuf * FS, vs_ = ks_ + 16384;

        // S = Q K^T  (scaled-log2 domain), pipelined fragment stream
        float sacc[16][4];
#pragma unroll
        for (int nt = 0; nt < 16; nt++)
#pragma unroll
            for (int c = 0; c < 4; c++) sacc[nt][c] = 0.f;
        {
            auto ldK = [&](uint32_t b[4], int kd, int nt2) {
                const int r = nt2 * 16 + ((lane >> 4) << 3) + (lane & 7);
                const int cb = kd * 32 + (((lane >> 3) & 1) << 4);
                ldsm4(b, ks_ + r * 128 + (cb ^ ((r & 7) << 4)));
            };
            uint32_t b[2][4];
            ldK(b[0], 0, 0);
#pragma unroll
            for (int step = 0; step < 32; step++) {
                const int kd = step >> 3, nt2 = step & 7, cb = step & 1;
                if (step < 31) ldK(b[cb ^ 1], (step + 1) >> 3, (step + 1) & 7);
                mma16816(sacc[nt2 * 2 + 0], qf[kd], b[cb][0], b[cb][1]);
                mma16816(sacc[nt2 * 2 + 1], qf[kd], b[cb][2], b[cb][3]);
            }
        }

        // online softmax (quad lanes share each row)
        float mx0 = sacc[0][0], mx1 = sacc[0][2];
#pragma unroll
        for (int nt = 0; nt < 16; nt++) {
            mx0 = fmaxf(mx0, fmaxf(sacc[nt][0], sacc[nt][1]));
            mx1 = fmaxf(mx1, fmaxf(sacc[nt][2], sacc[nt][3]));
        }
        mx0 = fmaxf(mx0, __shfl_xor_sync(0xffffffffu, mx0, 1));
        mx0 = fmaxf(mx0, __shfl_xor_sync(0xffffffffu, mx0, 2));
        mx1 = fmaxf(mx1, __shfl_xor_sync(0xffffffffu, mx1, 1));
        mx1 = fmaxf(mx1, __shfl_xor_sync(0xffffffffu, mx1, 2));
        const float mn0 = fmaxf(m0r, mx0), mn1 = fmaxf(m1r, mx1);
        const float al0 = ex2f(m0r - mn0);
        const float al1 = ex2f(m1r - mn1);
        m0r = mn0; m1r = mn1;
#pragma unroll
        for (int dn = 0; dn < 8; dn++) {
            oacc[dn][0] *= al0; oacc[dn][1] *= al0;
            oacc[dn][2] *= al1; oacc[dn][3] *= al1;
        }
        uint32_t pa[16][2];
#pragma unroll
        for (int nt = 0; nt < 16; nt++) {
            const float p0 = ex2f(sacc[nt][0] - mn0);
            const float p1 = ex2f(sacc[nt][1] - mn0);
            const float p2 = ex2f(sacc[nt][2] - mn1);
            const float p3 = ex2f(sacc[nt][3] - mn1);
            pa[nt][0] = packh2(p0, p1);
            pa[nt][1] = packh2(p2, p3);
        }

        // O += P V ; row sums via HMMA with ones-B; pipelined V fragments
        float rs[4] = {0.f, 0.f, 0.f, 0.f};
        {
            auto ldVt = [&](uint32_t b[4], int ks, int dn2) {
                const int r = ks * 16 + (lane & 15);
                const int cb = dn2 * 32 + ((lane >> 4) << 4);
                ldsm4t(b, vs_ + r * 128 + (cb ^ ((r & 7) << 4)));
            };
            uint32_t b[2][4], a[4];
            ldVt(b[0], 0, 0);
#pragma unroll
            for (int step = 0; step < 32; step++) {
                const int ks = step >> 2, dn2 = step & 3, cb = step & 1;
                if (step < 31) ldVt(b[cb ^ 1], (step + 1) >> 2, (step + 1) & 3);
                if (dn2 == 0) {
                    a[0] = pa[2 * ks][0]; a[1] = pa[2 * ks][1];
                    a[2] = pa[2 * ks + 1][0]; a[3] = pa[2 * ks + 1][1];
                    mma16816(rs, a, ONES, ONES);
                }
                mma16816(oacc[dn2 * 2 + 0], a, b[cb][0], b[cb][1]);
                mma16816(oacc[dn2 * 2 + 1], a, b[cb][2], b[cb][3]);
            }
        }
        l0 = l0 * al0 + rs[0];
        l1 = l1 * al1 + rs[2];

        cbuf = (cbuf == 2) ? 0 : cbuf + 1;
        lbuf = (lbuf == 2) ? 0 : lbuf + 1;
    }

    // normalize + write packed [b][s][h*64+d] fp16
    const int b_ = bh >> 4, h_ = bh & 15;
    __half* Ob = O + ((size_t)b_ * 2048 + q0) * 1024 + h_ * 64;
    const float inv0 = 1.f / l0, inv1 = 1.f / l1;
    const int r0 = (wid << 4) + (lane >> 2), colq = (lane & 3) * 2;
#pragma unroll
    for (int dn = 0; dn < 8; dn++) {
        const int col = dn * 8 + colq;
        *(uint32_t*)(Ob + (size_t)r0 * 1024 + col) =
            packh2(oacc[dn][0] * inv0, oacc[dn][1] * inv0);
        *(uint32_t*)(Ob + (size_t)(r0 + 8) * 1024 + col) =
            packh2(oacc[dn][2] * inv1, oacc[dn][3] * inv1);
    }
}

// ---------------------------------------------------------------------------
extern "C" void kernel_launch(void* const* d_in, const int* in_sizes, int n_in,
                              void* d_out, int out_size)
{
    const float* x  = (const float*)d_in[0];
    const float* wq = (const float*)d_in[1];
    const float* bq = (const float*)d_in[2];
    const float* wk = (const float*)d_in[3];
    const float* bk = (const float*)d_in[4];
    const float* wv = (const float*)d_in[5];
    const float* bv = (const float*)d_in[6];
    const float* wo = (const float*)d_in[7];
    const float* bo = (const float*)d_in[8];
    float* out = (float*)d_out;

    __half *xh, *wh, *qh, *kh, *vh, *aoh;
    cudaGetSymbolAddress((void**)&xh,  g_xh);
    cudaGetSymbolAddress((void**)&wh,  g_wh);
    cudaGetSymbolAddress((void**)&qh,  g_qh);
    cudaGetSymbolAddress((void**)&kh,  g_kh);
    cudaGetSymbolAddress((void**)&vh,  g_vh);
    cudaGetSymbolAddress((void**)&aoh, g_aoh);

    cudaFuncSetAttribute(gemm_qkv, cudaFuncAttributeMaxDynamicSharedMemorySize, GEMM_SMEM);
    cudaFuncSetAttribute(gemm_o,   cudaFuncAttributeMaxDynamicSharedMemorySize, GEMM_SMEM);
    cudaFuncSetAttribute(flash_hmma, cudaFuncAttributeMaxDynamicSharedMemorySize, FLASH_SMEM);

    f2h<<<8192, 256>>>(x, xh, 2097152);
    f2h4<<<dim3(1024, 4), 256>>>(wq, wk, wv, wo, wh);

    gemm_qkv<<<dim3(8, 64, 3), 256, GEMM_SMEM>>>(xh, wh, bq, bk, bv, qh, kh, vh);
    flash_hmma<<<dim3(16, 64), 256, FLASH_SMEM>>>(qh, kh, vh, aoh);
    gemm_o<<<dim3(8, 64), 256, GEMM_SMEM>>>(aoh, wh + 3145728, bo, out);
}

// round 7
// speedup vs baseline: 8.3309x; 1.0496x over previous
#include <cuda_runtime.h>
#include <cuda_fp16.h>
#include <cstdint>

#define CEXP 0.18033688011112042f   // 0.125 * log2(e), folded into Q projection

// fp16 scratch
static __device__ __align__(16) __half g_xh[8388608];   // x as fp16
static __device__ __align__(16) __half g_wh[4194304];   // wq|wk|wv|wo as fp16
static __device__ __align__(16) __half g_qh[8388608];   // [b][h][s][d], pre-scaled by CEXP
static __device__ __align__(16) __half g_kh[8388608];
static __device__ __align__(16) __half g_vh[8388608];
static __device__ __align__(16) __half g_aoh[8388608];  // [b][s][h*d]

// ---------------------------------------------------------------------------
__device__ __forceinline__ uint32_t smem_u32(const void* p) {
    uint32_t a;
    asm("{ .reg .u64 t; cvta.to.shared.u64 t, %1; cvt.u32.u64 %0, t; }" : "=r"(a) : "l"(p));
    return a;
}
#define CP16(s, g) asm volatile("cp.async.cg.shared.global [%0], [%1], 16;" :: "r"(s), "l"(g))
#define CP_COMMIT() asm volatile("cp.async.commit_group;" ::: "memory")
#define CP_WAIT0()  asm volatile("cp.async.wait_group 0;" ::: "memory")
#define CP_WAIT1()  asm volatile("cp.async.wait_group 1;" ::: "memory")
#define CP_WAIT2()  asm volatile("cp.async.wait_group 2;" ::: "memory")

__device__ __forceinline__ void ldsm4(uint32_t* r, uint32_t a) {
    asm volatile("ldmatrix.sync.aligned.m8n8.x4.shared.b16 {%0,%1,%2,%3}, [%4];"
                 : "=r"(r[0]), "=r"(r[1]), "=r"(r[2]), "=r"(r[3]) : "r"(a));
}
__device__ __forceinline__ void ldsm4t(uint32_t* r, uint32_t a) {
    asm volatile("ldmatrix.sync.aligned.m8n8.x4.trans.shared.b16 {%0,%1,%2,%3}, [%4];"
                 : "=r"(r[0]), "=r"(r[1]), "=r"(r[2]), "=r"(r[3]) : "r"(a));
}
__device__ __forceinline__ void mma16816(float* c, const uint32_t* a, uint32_t b0, uint32_t b1) {
    asm volatile("mma.sync.aligned.m16n8k16.row.col.f32.f16.f16.f32 "
                 "{%0,%1,%2,%3}, {%4,%5,%6,%7}, {%8,%9}, {%0,%1,%2,%3};"
                 : "+f"(c[0]), "+f"(c[1]), "+f"(c[2]), "+f"(c[3])
                 : "r"(a[0]), "r"(a[1]), "r"(a[2]), "r"(a[3]), "r"(b0), "r"(b1));
}
__device__ __forceinline__ uint32_t packh2(float lo, float hi) {
    uint32_t r;
    asm("cvt.rn.f16x2.f32 %0, %1, %2;" : "=r"(r) : "f"(hi), "f"(lo));
    return r;
}
__device__ __forceinline__ float ex2f(float x) {
    float r;
    asm("ex2.approx.f32 %0, %1;" : "=f"(r) : "f"(x));
    return r;
}

// ---------------------------------------------------------------------------
__global__ void f2h(const float* __restrict__ src, __half* __restrict__ dst, int n4) {
    const int i = blockIdx.x * blockDim.x + threadIdx.x;
    if (i < n4) {
        const float4 v = ((const float4*)src)[i];
        ((uint32_t*)dst)[2 * i + 0] = packh2(v.x, v.y);
        ((uint32_t*)dst)[2 * i + 1] = packh2(v.z, v.w);
    }
}
__global__ void f2h4(const float* __restrict__ s0, const float* __restrict__ s1,
                     const float* __restrict__ s2, const float* __restrict__ s3,
                     __half* __restrict__ dst) {
    const int i = blockIdx.x * blockDim.x + threadIdx.x;   // 0..262143
    const float* src = (blockIdx.y == 0) ? s0 : (blockIdx.y == 1) ? s1
                      : (blockIdx.y == 2) ? s2 : s3;
    const float4 v = ((const float4*)src)[i];
    uint32_t* d = (uint32_t*)(dst + (size_t)blockIdx.y * 1048576);
    d[2 * i + 0] = packh2(v.x, v.y);
    d[2 * i + 1] = packh2(v.z, v.w);
}

// ---------------------------------------------------------------------------
// Shared GEMM mainloop body: 128x128 tile, 3-stage cp.async, one barrier/stage,
// fragment-prefetch pipelined MMA stream. (unchanged from R6)
// ---------------------------------------------------------------------------
#define GS 32768
#define GEMM_SMEM (3 * GS)

struct GemmCtx {
    uint32_t sb;
    int tid, wid, lane, wm, wn;
};

__device__ __forceinline__ void gemm_mainloop(
    const GemmCtx& cx, const __half* __restrict__ A, const __half* __restrict__ W,
    int m0, int n0, float acc[2][8][4])
{
    const int tid = cx.tid, lane = cx.lane, wm = cx.wm, wn = cx.wn;
    const uint32_t sb = cx.sb;

    auto load_stage = [&](int s, int buf) {
        const uint32_t sA = sb + buf * GS, sB = sA + 16384;
        const __half* ga = A + (size_t)m0 * 1024 + s * 64;
        const __half* gb = W + (size_t)n0 * 1024 + s * 64;
#pragma unroll
        for (int i = 0; i < 4; i++) {
            const int id = tid + (i << 8), r = id >> 3, c = id & 7;
            CP16(sA + r * 128 + ((c * 16) ^ ((r & 7) << 4)), ga + (size_t)r * 1024 + c * 8);
        }
#pragma unroll
        for (int i = 0; i < 4; i++) {
            const int id = tid + (i << 8), r = id >> 3, c = id & 7;
            CP16(sB + r * 128 + ((c * 16) ^ ((r & 7) << 4)), gb + (size_t)r * 1024 + c * 8);
        }
    };

    load_stage(0, 0); CP_COMMIT();
    load_stage(1, 1); CP_COMMIT();

    int cbuf = 0, lbuf = 2;
    for (int s = 0; s < 16; s++) {
        if (s < 15) CP_WAIT1(); else CP_WAIT0();
        __syncthreads();
        if (s + 2 < 16) { load_stage(s + 2, lbuf); CP_COMMIT(); }

        const uint32_t sA = sb + cbuf * GS, sB = sA + 16384;
        auto ldA = [&](uint32_t a[2][4], int kd) {
#pragma unroll
            for (int mt = 0; mt < 2; mt++) {
                const int r = wm + mt * 16 + (lane & 15);
                const int cb = kd * 32 + ((lane >> 4) << 4);
                ldsm4(a[mt], sA + r * 128 + (cb ^ ((r & 7) << 4)));
            }
        };
        auto ldB = [&](uint32_t b[4], int kd, int nt2) {
            const int r = wn + nt2 * 16 + ((lane >> 4) << 3) + (lane & 7);
            const int cb = kd * 32 + (((lane >> 3) & 1) << 4);
            ldsm4(b, sB + r * 128 + (cb ^ ((r & 7) << 4)));
        };

        uint32_t a[2][2][4], b[2][4];
        ldA(a[0], 0);
        ldB(b[0], 0, 0);
#pragma unroll
        for (int step = 0; step < 16; step++) {
            const int kd = step >> 2, nt2 = step & 3;
            const int cb = step & 1, ab = kd & 1;
            if (step < 15) ldB(b[cb ^ 1], (step + 1) >> 2, (step + 1) & 3);
            if (nt2 == 1 && kd < 3) ldA(a[ab ^ 1], kd + 1);
#pragma unroll
            for (int mt = 0; mt < 2; mt++) {
                mma16816(acc[mt][nt2 * 2 + 0], a[ab][mt], b[cb][0], b[cb][1]);
                mma16816(acc[mt][nt2 * 2 + 1], a[ab][mt], b[cb][2], b[cb][3]);
            }
        }
        cbuf = (cbuf == 2) ? 0 : cbuf + 1;
        lbuf = (lbuf == 2) ? 0 : lbuf + 1;
    }
}

// Merged Q/K/V projection: grid.z selects weight/bias/output. fp16 head layout.
__global__ void __launch_bounds__(256, 2)
gemm_qkv(const __half* __restrict__ A, const __half* __restrict__ Wbase,
         const float* __restrict__ bq, const float* __restrict__ bk,
         const float* __restrict__ bv,
         __half* __restrict__ Cq, __half* __restrict__ Ck, __half* __restrict__ Cv)
{
    extern __shared__ char smem[];
    GemmCtx cx;
    cx.sb = smem_u32(smem);
    cx.tid = threadIdx.x; cx.wid = cx.tid >> 5; cx.lane = cx.tid & 31;
    cx.wm = (cx.wid & 3) << 5; cx.wn = (cx.wid >> 2) << 6;
    const int m0 = blockIdx.y << 7, n0 = blockIdx.x << 7;
    const int z = blockIdx.z;
    const __half* W = Wbase + ((size_t)z << 20);
    const float* bias = (z == 0) ? bq : (z == 1) ? bk : bv;
    __half* C = (z == 0) ? Cq : (z == 1) ? Ck : Cv;
    const float scale = (z == 0) ? CEXP : 1.0f;

    float acc[2][8][4];
#pragma unroll
    for (int mt = 0; mt < 2; mt++)
#pragma unroll
        for (int nt = 0; nt < 8; nt++)
#pragma unroll
            for (int c = 0; c < 4; c++) acc[mt][nt][c] = 0.f;

    gemm_mainloop(cx, A, W, m0, n0, acc);

    const int r0 = cx.lane >> 2, colq = (cx.lane & 3) * 2;
#pragma unroll
    for (int mt = 0; mt < 2; mt++) {
        const int row0 = m0 + cx.wm + mt * 16 + r0;
#pragma unroll
        for (int nt = 0; nt < 8; nt++) {
            const int col = n0 + cx.wn + nt * 8 + colq;
            const float2 bvv = *(const float2*)(bias + col);
            const float v0 = (acc[mt][nt][0] + bvv.x) * scale;
            const float v1 = (acc[mt][nt][1] + bvv.y) * scale;
            const float v2 = (acc[mt][nt][2] + bvv.x) * scale;
            const float v3 = (acc[mt][nt][3] + bvv.y) * scale;
            const int b = row0 >> 11, h = col >> 6, d = col & 63;
            const size_t hb = (size_t)(((b << 4) + h) << 11);
            *(uint32_t*)(C + (hb + (row0 & 2047)) * 64 + d)       = packh2(v0, v1);
            *(uint32_t*)(C + (hb + ((row0 + 8) & 2047)) * 64 + d) = packh2(v2, v3);
        }
    }
}

// Output projection: fp32 row-major out.
__global__ void __launch_bounds__(256, 2)
gemm_o(const __half* __restrict__ A, const __half* __restrict__ W,
       const float* __restrict__ bias, float* __restrict__ C)
{
    extern __shared__ char smem[];
    GemmCtx cx;
    cx.sb = smem_u32(smem);
    cx.tid = threadIdx.x; cx.wid = cx.tid >> 5; cx.lane = cx.tid & 31;
    cx.wm = (cx.wid & 3) << 5; cx.wn = (cx.wid >> 2) << 6;
    const int m0 = blockIdx.y << 7, n0 = blockIdx.x << 7;

    float acc[2][8][4];
#pragma unroll
    for (int mt = 0; mt < 2; mt++)
#pragma unroll
        for (int nt = 0; nt < 8; nt++)
#pragma unroll
            for (int c = 0; c < 4; c++) acc[mt][nt][c] = 0.f;

    gemm_mainloop(cx, A, W, m0, n0, acc);

    const int r0 = cx.lane >> 2, colq = (cx.lane & 3) * 2;
#pragma unroll
    for (int mt = 0; mt < 2; mt++) {
        const int row0 = m0 + cx.wm + mt * 16 + r0;
#pragma unroll
        for (int nt = 0; nt < 8; nt++) {
            const int col = n0 + cx.wn + nt * 8 + colq;
            const float2 bvv = *(const float2*)(bias + col);
            *(float2*)(C + (size_t)row0 * 1024 + col) =
                make_float2(acc[mt][nt][0] + bvv.x, acc[mt][nt][1] + bvv.y);
            *(float2*)(C + (size_t)(row0 + 8) * 1024 + col) =
                make_float2(acc[mt][nt][2] + bvv.x, acc[mt][nt][3] + bvv.y);
        }
    }
}

// ---------------------------------------------------------------------------
// Flash attention, fp16 HMMA, 64-key subtiles, 4-stage cp.async pipeline,
// one barrier/subtile, P aliased into S registers, 2 CTAs/SM.
// ---------------------------------------------------------------------------
#define FS 16384                     // bytes per KV stage (K 8K + V 8K), 64 keys
#define FLASH_SMEM (16384 + 4 * FS)  // Q 16K + 4 stages = 80K

__global__ void __launch_bounds__(256, 2)
flash_hmma(const __half* __restrict__ Q, const __half* __restrict__ K,
           const __half* __restrict__ V, __half* __restrict__ O)
{
    extern __shared__ char smem[];
    const uint32_t sb = smem_u32(smem);
    const uint32_t sQ = sb, sKV = sb + 16384;       // 4 stages of [K 8K | V 8K]
    const int tid = threadIdx.x, wid = tid >> 5, lane = tid & 31;
    const int q0 = blockIdx.x << 7, bh = blockIdx.y;
    const size_t base = (size_t)bh * (2048 * 64);
    const __half* Qb = Q + base + (size_t)q0 * 64;
    const __half* Kb = K + base;
    const __half* Vb = V + base;
    const uint32_t ONES = 0x3C003C00u;

#pragma unroll
    for (int i = 0; i < 4; i++) {                   // Q tile: 128 x 64 halves
        const int id = tid + (i << 8), r = id >> 3, c = id & 7;
        CP16(sQ + r * 128 + ((c * 16) ^ ((r & 7) << 4)), Qb + (size_t)r * 64 + c * 8);
    }
    // 64-key stage load: K 512 chunks + V 512 chunks, 2+2 per thread
    auto load_kv = [&](int t, int buf) {
        const __half* kg = Kb + (size_t)(t << 6) * 64;
        const __half* vg = Vb + (size_t)(t << 6) * 64;
        const uint32_t ks_ = sKV + buf * FS, vs_ = ks_ + 8192;
#pragma unroll
        for (int i = 0; i < 2; i++) {
            const int id = tid + (i << 8), r = id >> 3, c = id & 7;
            const uint32_t off = r * 128 + ((c * 16) ^ ((r & 7) << 4));
            CP16(ks_ + off, kg + (size_t)r * 64 + c * 8);
        }
#pragma unroll
        for (int i = 0; i < 2; i++) {
            const int id = tid + (i << 8), r = id >> 3, c = id & 7;
            const uint32_t off = r * 128 + ((c * 16) ^ ((r & 7) << 4));
            CP16(vs_ + off, vg + (size_t)r * 64 + c * 8);
        }
    };
    load_kv(0, 0); CP_COMMIT();                     // group0: Q + KV0
    load_kv(1, 1); CP_COMMIT();
    load_kv(2, 2); CP_COMMIT();
    CP_WAIT2();                                     // group0 done
    __syncthreads();

    uint32_t qf[4][4];
#pragma unroll
    for (int kd = 0; kd < 4; kd++) {
        const int r = (wid << 4) + (lane & 15);
        const int cb = kd * 32 + ((lane >> 4) << 4);
        ldsm4(qf[kd], sQ + r * 128 + (cb ^ ((r & 7) << 4)));
    }

    float oacc[8][4];
#pragma unroll
    for (int dn = 0; dn < 8; dn++)
#pragma unroll
        for (int c = 0; c < 4; c++) oacc[dn][c] = 0.f;
    float m0r = -1.0e30f, m1r = -1.0e30f, l0 = 0.f, l1 = 0.f;

    for (int t = 0; t < 32; t++) {
        if (t > 0) {
            CP_WAIT2();                             // groups 0..t complete
            __syncthreads();                        // buf (t-1)&3 free for reload
        }
        if (t + 3 < 32) load_kv(t + 3, (t + 3) & 3);
        CP_COMMIT();                                // empty group ok: keeps count
        const uint32_t ks_ = sKV + (t & 3) * FS, vs_ = ks_ + 8192;

        // S = Q K^T  (16q x 64k, scaled-log2 domain), pipelined fragments
        float sacc[8][4];
#pragma unroll
        for (int nt = 0; nt < 8; nt++)
#pragma unroll
            for (int c = 0; c < 4; c++) sacc[nt][c] = 0.f;
        {
            auto ldK = [&](uint32_t b[4], int kd, int nt2) {
                const int r = nt2 * 16 + ((lane >> 4) << 3) + (lane & 7);
                const int cb = kd * 32 + (((lane >> 3) & 1) << 4);
                ldsm4(b, ks_ + r * 128 + (cb ^ ((r & 7) << 4)));
            };
            uint32_t b[2][4];
            ldK(b[0], 0, 0);
#pragma unroll
            for (int step = 0; step < 16; step++) {
                const int kd = step >> 2, nt2 = step & 3, cb = step & 1;
                if (step < 15) ldK(b[cb ^ 1], (step + 1) >> 2, (step + 1) & 3);
                mma16816(sacc[nt2 * 2 + 0], qf[kd], b[cb][0], b[cb][1]);
                mma16816(sacc[nt2 * 2 + 1], qf[kd], b[cb][2], b[cb][3]);
            }
        }

        // online softmax over 64 keys (quad lanes share each row)
        float mx0 = sacc[0][0], mx1 = sacc[0][2];
#pragma unroll
        for (int nt = 0; nt < 8; nt++) {
            mx0 = fmaxf(mx0, fmaxf(sacc[nt][0], sacc[nt][1]));
            mx1 = fmaxf(mx1, fmaxf(sacc[nt][2], sacc[nt][3]));
        }
        mx0 = fmaxf(mx0, __shfl_xor_sync(0xffffffffu, mx0, 1));
        mx0 = fmaxf(mx0, __shfl_xor_sync(0xffffffffu, mx0, 2));
        mx1 = fmaxf(mx1, __shfl_xor_sync(0xffffffffu, mx1, 1));
        mx1 = fmaxf(mx1, __shfl_xor_sync(0xffffffffu, mx1, 2));
        const float mn0 = fmaxf(m0r, mx0), mn1 = fmaxf(m1r, mx1);
        const float al0 = ex2f(m0r - mn0);
        const float al1 = ex2f(m1r - mn1);
        m0r = mn0; m1r = mn1;
#pragma unroll
        for (int dn = 0; dn < 8; dn++) {
            oacc[dn][0] *= al0; oacc[dn][1] *= al0;
            oacc[dn][2] *= al1; oacc[dn][3] *= al1;
        }
        // exp via MUFU; pack P back INTO sacc registers (alias)
#pragma unroll
        for (int nt = 0; nt < 8; nt++) {
            const float p0 = ex2f(sacc[nt][0] - mn0);
            const float p1 = ex2f(sacc[nt][1] - mn0);
            const float p2 = ex2f(sacc[nt][2] - mn1);
            const float p3 = ex2f(sacc[nt][3] - mn1);
            sacc[nt][0] = __uint_as_float(packh2(p0, p1));
            sacc[nt][2] = __uint_as_float(packh2(p2, p3));
        }

        // O += P V (16q x 64k x 64d); row sums via ones-B HMMA
        float rs[4] = {0.f, 0.f, 0.f, 0.f};
        {
            auto ldVt = [&](uint32_t b[4], int ks, int dn2) {
                const int r = ks * 16 + (lane & 15);
                const int cb = dn2 * 32 + ((lane >> 4) << 4);
                ldsm4t(b, vs_ + r * 128 + (cb ^ ((r & 7) << 4)));
            };
            uint32_t b[2][4], a[4];
            ldVt(b[0], 0, 0);
#pragma unroll
            for (int step = 0; step < 16; step++) {
                const int ks = step >> 2, dn2 = step & 3, cb = step & 1;
                if (step < 15) ldVt(b[cb ^ 1], (step + 1) >> 2, (step + 1) & 3);
                if (dn2 == 0) {
                    a[0] = __float_as_uint(sacc[2 * ks][0]);
                    a[1] = __float_as_uint(sacc[2 * ks][2]);
                    a[2] = __float_as_uint(sacc[2 * ks + 1][0]);
                    a[3] = __float_as_uint(sacc[2 * ks + 1][2]);
                    mma16816(rs, a, ONES, ONES);
                }
                mma16816(oacc[dn2 * 2 + 0], a, b[cb][0], b[cb][1]);
                mma16816(oacc[dn2 * 2 + 1], a, b[cb][2], b[cb][3]);
            }
        }
        l0 = l0 * al0 + rs[0];
        l1 = l1 * al1 + rs[2];
    }

    // normalize + write packed [b][s][h*64+d] fp16
    const int b_ = bh >> 4, h_ = bh & 15;
    __half* Ob = O + ((size_t)b_ * 2048 + q0) * 1024 + h_ * 64;
    const float inv0 = 1.f / l0, inv1 = 1.f / l1;
    const int r0 = (wid << 4) + (lane >> 2), colq = (lane & 3) * 2;
#pragma unroll
    for (int dn = 0; dn < 8; dn++) {
        const int col = dn * 8 + colq;
        *(uint32_t*)(Ob + (size_t)r0 * 1024 + col) =
            packh2(oacc[dn][0] * inv0, oacc[dn][1] * inv0);
        *(uint32_t*)(Ob + (size_t)(r0 + 8) * 1024 + col) =
            packh2(oacc[dn][2] * inv1, oacc[dn][3] * inv1);
    }
}

// ---------------------------------------------------------------------------
extern "C" void kernel_launch(void* const* d_in, const int* in_sizes, int n_in,
                              void* d_out, int out_size)
{
    const float* x  = (const float*)d_in[0];
    const float* wq = (const float*)d_in[1];
    const float* bq = (const float*)d_in[2];
    const float* wk = (const float*)d_in[3];
    const float* bk = (const float*)d_in[4];
    const float* wv = (const float*)d_in[5];
    const float* bv = (const float*)d_in[6];
    const float* wo = (const float*)d_in[7];
    const float* bo = (const float*)d_in[8];
    float* out = (float*)d_out;

    __half *xh, *wh, *qh, *kh, *vh, *aoh;
    cudaGetSymbolAddress((void**)&xh,  g_xh);
    cudaGetSymbolAddress((void**)&wh,  g_wh);
    cudaGetSymbolAddress((void**)&qh,  g_qh);
    cudaGetSymbolAddress((void**)&kh,  g_kh);
    cudaGetSymbolAddress((void**)&vh,  g_vh);
    cudaGetSymbolAddress((void**)&aoh, g_aoh);

    cudaFuncSetAttribute(gemm_qkv, cudaFuncAttributeMaxDynamicSharedMemorySize, GEMM_SMEM);
    cudaFuncSetAttribute(gemm_o,   cudaFuncAttributeMaxDynamicSharedMemorySize, GEMM_SMEM);
    cudaFuncSetAttribute(flash_hmma, cudaFuncAttributeMaxDynamicSharedMemorySize, FLASH_SMEM);

    f2h<<<8192, 256>>>(x, xh, 2097152);
    f2h4<<<dim3(1024, 4), 256>>>(wq, wk, wv, wo, wh);

    gemm_qkv<<<dim3(8, 64, 3), 256, GEMM_SMEM>>>(xh, wh, bq, bk, bv, qh, kh, vh);
    flash_hmma<<<dim3(16, 64), 256, FLASH_SMEM>>>(qh, kh, vh, aoh);
    gemm_o<<<dim3(8, 64), 256, GEMM_SMEM>>>(aoh, wh + 3145728, bo, out);
}

// round 8
// speedup vs baseline: 8.4400x; 1.0131x over previous
#include <cuda_runtime.h>
#include <cuda_fp16.h>
#include <cstdint>

#define CEXP 0.18033688011112042f   // 0.125 * log2(e), folded into Q projection

// fp16 scratch
static __device__ __align__(16) __half g_xh[8388608];   // x as fp16
static __device__ __align__(16) __half g_wh[4194304];   // wq|wk|wv|wo as fp16
static __device__ __align__(16) __half g_qh[8388608];   // [b][h][s][d], pre-scaled by CEXP
static __device__ __align__(16) __half g_kh[8388608];
static __device__ __align__(16) __half g_vh[8388608];
static __device__ __align__(16) __half g_aoh[8388608];  // [b][s][h*d]

// ---------------------------------------------------------------------------
__device__ __forceinline__ uint32_t smem_u32(const void* p) {
    uint32_t a;
    asm("{ .reg .u64 t; cvta.to.shared.u64 t, %1; cvt.u32.u64 %0, t; }" : "=r"(a) : "l"(p));
    return a;
}
#define CP16(s, g) asm volatile("cp.async.cg.shared.global [%0], [%1], 16;" :: "r"(s), "l"(g))
#define CP_COMMIT() asm volatile("cp.async.commit_group;" ::: "memory")
#define CP_WAIT0()  asm volatile("cp.async.wait_group 0;" ::: "memory")
#define CP_WAIT1()  asm volatile("cp.async.wait_group 1;" ::: "memory")

__device__ __forceinline__ void ldsm4(uint32_t* r, uint32_t a) {
    asm volatile("ldmatrix.sync.aligned.m8n8.x4.shared.b16 {%0,%1,%2,%3}, [%4];"
                 : "=r"(r[0]), "=r"(r[1]), "=r"(r[2]), "=r"(r[3]) : "r"(a));
}
__device__ __forceinline__ void ldsm4t(uint32_t* r, uint32_t a) {
    asm volatile("ldmatrix.sync.aligned.m8n8.x4.trans.shared.b16 {%0,%1,%2,%3}, [%4];"
                 : "=r"(r[0]), "=r"(r[1]), "=r"(r[2]), "=r"(r[3]) : "r"(a));
}
__device__ __forceinline__ void mma16816(float* c, const uint32_t* a, uint32_t b0, uint32_t b1) {
    asm volatile("mma.sync.aligned.m16n8k16.row.col.f32.f16.f16.f32 "
                 "{%0,%1,%2,%3}, {%4,%5,%6,%7}, {%8,%9}, {%0,%1,%2,%3};"
                 : "+f"(c[0]), "+f"(c[1]), "+f"(c[2]), "+f"(c[3])
                 : "r"(a[0]), "r"(a[1]), "r"(a[2]), "r"(a[3]), "r"(b0), "r"(b1));
}
__device__ __forceinline__ uint32_t packh2(float lo, float hi) {
    uint32_t r;
    asm("cvt.rn.f16x2.f32 %0, %1, %2;" : "=r"(r) : "f"(hi), "f"(lo));
    return r;
}
__device__ __forceinline__ uint32_t hmax2(uint32_t a, uint32_t b) {
    uint32_t r;
    asm("max.f16x2 %0, %1, %2;" : "=r"(r) : "r"(a), "r"(b));
    return r;
}
__device__ __forceinline__ float ex2f(float x) {
    float r;
    asm("ex2.approx.f32 %0, %1;" : "=f"(r) : "f"(x));
    return r;
}

// ---------------------------------------------------------------------------
__global__ void f2h(const float* __restrict__ src, __half* __restrict__ dst, int n4) {
    const int i = blockIdx.x * blockDim.x + threadIdx.x;
    if (i < n4) {
        const float4 v = ((const float4*)src)[i];
        ((uint32_t*)dst)[2 * i + 0] = packh2(v.x, v.y);
        ((uint32_t*)dst)[2 * i + 1] = packh2(v.z, v.w);
    }
}
__global__ void f2h4(const float* __restrict__ s0, const float* __restrict__ s1,
                     const float* __restrict__ s2, const float* __restrict__ s3,
                     __half* __restrict__ dst) {
    const int i = blockIdx.x * blockDim.x + threadIdx.x;   // 0..262143
    const float* src = (blockIdx.y == 0) ? s0 : (blockIdx.y == 1) ? s1
                      : (blockIdx.y == 2) ? s2 : s3;
    const float4 v = ((const float4*)src)[i];
    uint32_t* d = (uint32_t*)(dst + (size_t)blockIdx.y * 1048576);
    d[2 * i + 0] = packh2(v.x, v.y);
    d[2 * i + 1] = packh2(v.z, v.w);
}

// ---------------------------------------------------------------------------
// Shared GEMM mainloop: 128x128 tile, 3-stage cp.async, one barrier/stage,
// fragment-prefetch MMA stream, lane-const addressing, incremental pointers.
// ---------------------------------------------------------------------------
#define GS 32768
#define GEMM_SMEM (3 * GS)

struct GemmCtx {
    uint32_t sb;
    int tid, wid, lane, wm, wn;
};

__device__ __forceinline__ void gemm_mainloop(
    const GemmCtx& cx, const __half* __restrict__ A, const __half* __restrict__ W,
    int m0, int n0, float acc[2][8][4])
{
    const int tid = cx.tid, lane = cx.lane, wm = cx.wm, wn = cx.wn;
    const uint32_t sb = cx.sb;

    // tid-constant loader offsets (same pattern for A and B: 512 rows x 8 chunks)
    int goff[4], soff[4];
#pragma unroll
    for (int i = 0; i < 4; i++) {
        const int id = tid + (i << 8), r = id >> 3, c = id & 7;
        goff[i] = r * 1024 + c * 8;
        soff[i] = r * 128 + ((c * 16) ^ ((r & 7) << 4));
    }
    auto load_stage = [&](const __half* ga, const __half* gb, int buf) {
        const uint32_t sA = sb + buf * GS, sB = sA + 16384;
#pragma unroll
        for (int i = 0; i < 4; i++) CP16(sA + soff[i], ga + goff[i]);
#pragma unroll
        for (int i = 0; i < 4; i++) CP16(sB + soff[i], gb + goff[i]);
    };

    const __half* ap = A + (size_t)m0 * 1024;
    const __half* wp = W + (size_t)n0 * 1024;
    load_stage(ap, wp, 0); CP_COMMIT(); ap += 64; wp += 64;
    load_stage(ap, wp, 1); CP_COMMIT(); ap += 64; wp += 64;

    // lane-constant fragment address parts
    const int la15 = lane & 15;
    const int lbr  = ((lane >> 4) << 3) + (lane & 7);
    const uint32_t axy = (uint32_t)(((lane >> 4) << 4) ^ ((la15 & 7) << 4));
    const uint32_t bxy = (uint32_t)((((lane >> 3) & 1) << 4) ^ ((lbr & 7) << 4));
    const int aoff0 = (wm + la15) * 128, aoff1 = (wm + 16 + la15) * 128;
    const int boff  = (wn + lbr) * 128;

    int cbuf = 0, lbuf = 2;
    for (int s = 0; s < 16; s++) {
        if (s < 15) CP_WAIT1(); else CP_WAIT0();
        __syncthreads();
        if (s + 2 < 16) { load_stage(ap, wp, lbuf); CP_COMMIT(); ap += 64; wp += 64; }

        const uint32_t sA = sb + cbuf * GS, sB = sA + 16384;
        auto ldA = [&](uint32_t a[2][4], int kd) {
            const uint32_t kk = (uint32_t)(kd * 32) ^ axy;
            ldsm4(a[0], sA + aoff0 + kk);
            ldsm4(a[1], sA + aoff1 + kk);
        };
        auto ldB = [&](uint32_t b[4], int kd, int nt2) {
            ldsm4(b, sB + boff + nt2 * 2048 + ((uint32_t)(kd * 32) ^ bxy));
        };

        uint32_t a[2][2][4], b[2][4];
        ldA(a[0], 0);
        ldB(b[0], 0, 0);
#pragma unroll
        for (int step = 0; step < 16; step++) {
            const int kd = step >> 2, nt2 = step & 3;
            const int cb = step & 1, ab = kd & 1;
            if (step < 15) ldB(b[cb ^ 1], (step + 1) >> 2, (step + 1) & 3);
            if (nt2 == 1 && kd < 3) ldA(a[ab ^ 1], kd + 1);
#pragma unroll
            for (int mt = 0; mt < 2; mt++) {
                mma16816(acc[mt][nt2 * 2 + 0], a[ab][mt], b[cb][0], b[cb][1]);
                mma16816(acc[mt][nt2 * 2 + 1], a[ab][mt], b[cb][2], b[cb][3]);
            }
        }
        cbuf = (cbuf == 2) ? 0 : cbuf + 1;
        lbuf = (lbuf == 2) ? 0 : lbuf + 1;
    }
}

// Merged Q/K/V projection: grid.z selects weight/bias/output. fp16 head layout.
__global__ void __launch_bounds__(256, 2)
gemm_qkv(const __half* __restrict__ A, const __half* __restrict__ Wbase,
         const float* __restrict__ bq, const float* __restrict__ bk,
         const float* __restrict__ bv,
         __half* __restrict__ Cq, __half* __restrict__ Ck, __half* __restrict__ Cv)
{
    extern __shared__ char smem[];
    GemmCtx cx;
    cx.sb = smem_u32(smem);
    cx.tid = threadIdx.x; cx.wid = cx.tid >> 5; cx.lane = cx.tid & 31;
    cx.wm = (cx.wid & 3) << 5; cx.wn = (cx.wid >> 2) << 6;
    const int m0 = blockIdx.y << 7, n0 = blockIdx.x << 7;
    const int z = blockIdx.z;
    const __half* W = Wbase + ((size_t)z << 20);
    const float* bias = (z == 0) ? bq : (z == 1) ? bk : bv;
    __half* C = (z == 0) ? Cq : (z == 1) ? Ck : Cv;
    const float scale = (z == 0) ? CEXP : 1.0f;

    float acc[2][8][4];
#pragma unroll
    for (int mt = 0; mt < 2; mt++)
#pragma unroll
        for (int nt = 0; nt < 8; nt++)
#pragma unroll
            for (int c = 0; c < 4; c++) acc[mt][nt][c] = 0.f;

    gemm_mainloop(cx, A, W, m0, n0, acc);

    const int r0 = cx.lane >> 2, colq = (cx.lane & 3) * 2;
#pragma unroll
    for (int mt = 0; mt < 2; mt++) {
        const int row0 = m0 + cx.wm + mt * 16 + r0;
#pragma unroll
        for (int nt = 0; nt < 8; nt++) {
            const int col = n0 + cx.wn + nt * 8 + colq;
            const float2 bvv = *(const float2*)(bias + col);
            const float v0 = (acc[mt][nt][0] + bvv.x) * scale;
            const float v1 = (acc[mt][nt][1] + bvv.y) * scale;
            const float v2 = (acc[mt][nt][2] + bvv.x) * scale;
            const float v3 = (acc[mt][nt][3] + bvv.y) * scale;
            const int b = row0 >> 11, h = col >> 6, d = col & 63;
            const size_t hb = (size_t)(((b << 4) + h) << 11);
            *(uint32_t*)(C + (hb + (row0 & 2047)) * 64 + d)       = packh2(v0, v1);
            *(uint32_t*)(C + (hb + ((row0 + 8) & 2047)) * 64 + d) = packh2(v2, v3);
        }
    }
}

// Output projection: fp32 row-major out.
__global__ void __launch_bounds__(256, 2)
gemm_o(const __half* __restrict__ A, const __half* __restrict__ W,
       const float* __restrict__ bias, float* __restrict__ C)
{
    extern __shared__ char smem[];
    GemmCtx cx;
    cx.sb = smem_u32(smem);
    cx.tid = threadIdx.x; cx.wid = cx.tid >> 5; cx.lane = cx.tid & 31;
    cx.wm = (cx.wid & 3) << 5; cx.wn = (cx.wid >> 2) << 6;
    const int m0 = blockIdx.y << 7, n0 = blockIdx.x << 7;

    float acc[2][8][4];
#pragma unroll
    for (int mt = 0; mt < 2; mt++)
#pragma unroll
        for (int nt = 0; nt < 8; nt++)
#pragma unroll
            for (int c = 0; c < 4; c++) acc[mt][nt][c] = 0.f;

    gemm_mainloop(cx, A, W, m0, n0, acc);

    const int r0 = cx.lane >> 2, colq = (cx.lane & 3) * 2;
#pragma unroll
    for (int mt = 0; mt < 2; mt++) {
        const int row0 = m0 + cx.wm + mt * 16 + r0;
#pragma unroll
        for (int nt = 0; nt < 8; nt++) {
            const int col = n0 + cx.wn + nt * 8 + colq;
            const float2 bvv = *(const float2*)(bias + col);
            *(float2*)(C + (size_t)row0 * 1024 + col) =
                make_float2(acc[mt][nt][0] + bvv.x, acc[mt][nt][1] + bvv.y);
            *(float2*)(C + (size_t)(row0 + 8) * 1024 + col) =
                make_float2(acc[mt][nt][2] + bvv.x, acc[mt][nt][3] + bvv.y);
        }
    }
}

// ---------------------------------------------------------------------------
// Flash attention, fp16 HMMA, 64-key subtiles, 4-stage ring, one barrier per
// PAIR of tiles, half2-packed max shuffles, lane-const addressing, 2 CTAs/SM.
// ---------------------------------------------------------------------------
#define FS 16384                     // bytes per KV stage (K 8K + V 8K), 64 keys
#define FLASH_SMEM (16384 + 4 * FS)  // Q 16K + 4 stages = 80K

__global__ void __launch_bounds__(256, 2)
flash_hmma(const __half* __restrict__ Q, const __half* __restrict__ K,
           const __half* __restrict__ V, __half* __restrict__ O)
{
    extern __shared__ char smem[];
    const uint32_t sb = smem_u32(smem);
    const uint32_t sQ = sb, sKV = sb + 16384;       // 4 stages of [K 8K | V 8K]
    const int tid = threadIdx.x, wid = tid >> 5, lane = tid & 31;
    const int q0 = blockIdx.x << 7, bh = blockIdx.y;
    const size_t base = (size_t)bh * (2048 * 64);
    const __half* Qb = Q + base + (size_t)q0 * 64;
    const uint32_t ONES = 0x3C003C00u;

    // tid-constant loader offsets (64 rows x 8 chunks per K or V half-stage)
    int g0, g1, s0, s1;
    {
        const int r0_ = tid >> 3, c_ = tid & 7;
        const int r1_ = (tid + 256) >> 3;
        g0 = r0_ * 64 + c_ * 8;  s0 = r0_ * 128 + ((c_ * 16) ^ ((r0_ & 7) << 4));
        g1 = r1_ * 64 + c_ * 8;  s1 = r1_ * 128 + ((c_ * 16) ^ ((r1_ & 7) << 4));
    }

#pragma unroll
    for (int i = 0; i < 4; i++) {                   // Q tile: 128 x 64 halves
        const int id = tid + (i << 8), r = id >> 3, c = id & 7;
        CP16(sQ + r * 128 + ((c * 16) ^ ((r & 7) << 4)), Qb + (size_t)r * 64 + c * 8);
    }
    auto load_kv = [&](const __half* kp, const __half* vp, int buf) {
        const uint32_t ks_ = sKV + buf * FS, vs_ = ks_ + 8192;
        CP16(ks_ + s0, kp + g0);
        CP16(ks_ + s1, kp + g1);
        CP16(vs_ + s0, vp + g0);
        CP16(vs_ + s1, vp + g1);
    };
    const __half* kp = K + base;
    const __half* vp = V + base;
    load_kv(kp, vp, 0); CP_COMMIT();                // g0 incl Q
    load_kv(kp + 4096, vp + 4096, 1); CP_COMMIT();
    kp += 8192; vp += 8192;                         // -> tile 2
    CP_WAIT0();
    __syncthreads();

    uint32_t qf[4][4];
#pragma unroll
    for (int kd = 0; kd < 4; kd++) {
        const int r = (wid << 4) + (lane & 15);
        const int cb = kd * 32 + ((lane >> 4) << 4);
        ldsm4(qf[kd], sQ + r * 128 + (cb ^ ((r & 7) << 4)));
    }

    // lane-const fragment address parts
    const int klr  = ((lane >> 4) << 3) + (lane & 7);
    const int koff = klr * 128;
    const uint32_t kxy = (uint32_t)((((lane >> 3) & 1) << 4) ^ ((klr & 7) << 4));
    const int voff = (lane & 15) * 128;
    const uint32_t vxy = (uint32_t)(((lane >> 4) << 4) ^ ((lane & 7) << 4));

    float oacc[8][4];
#pragma unroll
    for (int dn = 0; dn < 8; dn++)
#pragma unroll
        for (int c = 0; c < 4; c++) oacc[dn][c] = 0.f;
    float m0r = -1.0e30f, m1r = -1.0e30f, l0 = 0.f, l1 = 0.f;

    // one 64-key tile: S-mma, online softmax, PV
    auto attn_tile = [&](uint32_t ks_, uint32_t vs_) {
        float sacc[8][4];
#pragma unroll
        for (int nt = 0; nt < 8; nt++)
#pragma unroll
            for (int c = 0; c < 4; c++) sacc[nt][c] = 0.f;
        {
            uint32_t b[2][4];
            auto ldK = [&](uint32_t* bb, int step) {
                const int kd = step >> 2, nt2 = step & 3;
                ldsm4(bb, ks_ + koff + nt2 * 2048 + ((uint32_t)(kd * 32) ^ kxy));
            };
            ldK(b[0], 0);
#pragma unroll
            for (int step = 0; step < 16; step++) {
                const int nt2 = step & 3, cb = step & 1, kd = step >> 2;
                if (step < 15) ldK(b[cb ^ 1], step + 1);
                mma16816(sacc[nt2 * 2 + 0], qf[kd], b[cb][0], b[cb][1]);
                mma16816(sacc[nt2 * 2 + 1], qf[kd], b[cb][2], b[cb][3]);
            }
        }

        // online softmax (quad lanes share each row); packed-half2 shuffle max
        float mx0 = sacc[0][0], mx1 = sacc[0][2];
#pragma unroll
        for (int nt = 0; nt < 8; nt++) {
            mx0 = fmaxf(mx0, fmaxf(sacc[nt][0], sacc[nt][1]));
            mx1 = fmaxf(mx1, fmaxf(sacc[nt][2], sacc[nt][3]));
        }
        uint32_t mp = packh2(mx0, mx1);
        mp = hmax2(mp, __shfl_xor_sync(0xffffffffu, mp, 1));
        mp = hmax2(mp, __shfl_xor_sync(0xffffffffu, mp, 2));
        const __half2 mh = *(__half2*)&mp;
        mx0 = __low2float(mh); mx1 = __high2float(mh);
        // (m rounding is safe: common factor cancels in o = sum(p v)/sum(p))
        const float mn0 = fmaxf(m0r, mx0), mn1 = fmaxf(m1r, mx1);
        const float al0 = ex2f(m0r - mn0);
        const float al1 = ex2f(m1r - mn1);
        m0r = mn0; m1r = mn1;
#pragma unroll
        for (int dn = 0; dn < 8; dn++) {
            oacc[dn][0] *= al0; oacc[dn][1] *= al0;
            oacc[dn][2] *= al1; oacc[dn][3] *= al1;
        }
        // exp via MUFU; pack P back into sacc registers (alias)
#pragma unroll
        for (int nt = 0; nt < 8; nt++) {
            const float p0 = ex2f(sacc[nt][0] - mn0);
            const float p1 = ex2f(sacc[nt][1] - mn0);
            const float p2 = ex2f(sacc[nt][2] - mn1);
            const float p3 = ex2f(sacc[nt][3] - mn1);
            sacc[nt][0] = __uint_as_float(packh2(p0, p1));
            sacc[nt][2] = __uint_as_float(packh2(p2, p3));
        }

        // O += P V; row sums via ones-B HMMA
        float rs[4] = {0.f, 0.f, 0.f, 0.f};
        {
            uint32_t b[2][4], a[4];
            auto ldVt = [&](uint32_t* bb, int step) {
                const int ks = step >> 2, dn2 = step & 3;
                ldsm4t(bb, vs_ + voff + ks * 2048 + ((uint32_t)(dn2 * 32) ^ vxy));
            };
            ldVt(b[0], 0);
#pragma unroll
            for (int step = 0; step < 16; step++) {
                const int ks = step >> 2, dn2 = step & 3, cb = step & 1;
                if (step < 15) ldVt(b[cb ^ 1], step + 1);
                if (dn2 == 0) {
                    a[0] = __float_as_uint(sacc[2 * ks][0]);
                    a[1] = __float_as_uint(sacc[2 * ks][2]);
                    a[2] = __float_as_uint(sacc[2 * ks + 1][0]);
                    a[3] = __float_as_uint(sacc[2 * ks + 1][2]);
                    mma16816(rs, a, ONES, ONES);
                }
                mma16816(oacc[dn2 * 2 + 0], a, b[cb][0], b[cb][1]);
                mma16816(oacc[dn2 * 2 + 1], a, b[cb][2], b[cb][3]);
            }
        }
        l0 = l0 * al0 + rs[0];
        l1 = l1 * al1 + rs[2];
    };

    // main loop: 16 pairs of 64-key tiles; one wait+barrier per pair
    for (int p = 0; p < 16; p++) {
        if (p > 0) {
            CP_WAIT0();                             // this pair's loads done
            __syncthreads();                        // pair p-1 consumed by all
        }
        if (p < 15) {                               // load pair p+1 into p-1's bufs
            load_kv(kp, vp, (2 * p + 2) & 3); CP_COMMIT();
            load_kv(kp + 4096, vp + 4096, (2 * p + 3) & 3); CP_COMMIT();
            kp += 8192; vp += 8192;
        }
        const uint32_t b0 = sKV + ((2 * p) & 3) * FS;
        const uint32_t b1 = sKV + ((2 * p + 1) & 3) * FS;
        attn_tile(b0, b0 + 8192);
        attn_tile(b1, b1 + 8192);
    }

    // normalize + write packed [b][s][h*64+d] fp16
    const int b_ = bh >> 4, h_ = bh & 15;
    __half* Ob = O + ((size_t)b_ * 2048 + q0) * 1024 + h_ * 64;
    const float inv0 = 1.f / l0, inv1 = 1.f / l1;
    const int r0 = (wid << 4) + (lane >> 2), colq = (lane & 3) * 2;
#pragma unroll
    for (int dn = 0; dn < 8; dn++) {
        const int col = dn * 8 + colq;
        *(uint32_t*)(Ob + (size_t)r0 * 1024 + col) =
            packh2(oacc[dn][0] * inv0, oacc[dn][1] * inv0);
        *(uint32_t*)(Ob + (size_t)(r0 + 8) * 1024 + col) =
            packh2(oacc[dn][2] * inv1, oacc[dn][3] * inv1);
    }
}

// ---------------------------------------------------------------------------
extern "C" void kernel_launch(void* const* d_in, const int* in_sizes, int n_in,
                              void* d_out, int out_size)
{
    const float* x  = (const float*)d_in[0];
    const float* wq = (const float*)d_in[1];
    const float* bq = (const float*)d_in[2];
    const float* wk = (const float*)d_in[3];
    const float* bk = (const float*)d_in[4];
    const float* wv = (const float*)d_in[5];
    const float* bv = (const float*)d_in[6];
    const float* wo = (const float*)d_in[7];
    const float* bo = (const float*)d_in[8];
    float* out = (float*)d_out;

    __half *xh, *wh, *qh, *kh, *vh, *aoh;
    cudaGetSymbolAddress((void**)&xh,  g_xh);
    cudaGetSymbolAddress((void**)&wh,  g_wh);
    cudaGetSymbolAddress((void**)&qh,  g_qh);
    cudaGetSymbolAddress((void**)&kh,  g_kh);
    cudaGetSymbolAddress((void**)&vh,  g_vh);
    cudaGetSymbolAddress((void**)&aoh, g_aoh);

    cudaFuncSetAttribute(gemm_qkv, cudaFuncAttributeMaxDynamicSharedMemorySize, GEMM_SMEM);
    cudaFuncSetAttribute(gemm_o,   cudaFuncAttributeMaxDynamicSharedMemorySize, GEMM_SMEM);
    cudaFuncSetAttribute(flash_hmma, cudaFuncAttributeMaxDynamicSharedMemorySize, FLASH_SMEM);

    f2h<<<8192, 256>>>(x, xh, 2097152);
    f2h4<<<dim3(1024, 4), 256>>>(wq, wk, wv, wo, wh);

    gemm_qkv<<<dim3(8, 64, 3), 256, GEMM_SMEM>>>(xh, wh, bq, bk, bv, qh, kh, vh);
    flash_hmma<<<dim3(16, 64), 256, FLASH_SMEM>>>(qh, kh, vh, aoh);
    gemm_o<<<dim3(8, 64), 256, GEMM_SMEM>>>(aoh, wh + 3145728, bo, out);
}

// round 9
// speedup vs baseline: 8.8189x; 1.0449x over previous
#include <cuda_runtime.h>
#include <cuda_fp16.h>
#include <cstdint>

#define CEXP 0.18033688011112042f   // 0.125 * log2(e), folded into Q projection

// fp16 scratch
static __device__ __align__(16) __half g_xh[8388608];   // x as fp16
static __device__ __align__(16) __half g_wh[4194304];   // wq|wk|wv|wo as fp16
static __device__ __align__(16) __half g_qh[8388608];   // [b][h][s][d], pre-scaled by CEXP
static __device__ __align__(16) __half g_kh[8388608];
static __device__ __align__(16) __half g_vh[8388608];
static __device__ __align__(16) __half g_aoh[8388608];  // [b][s][h*d]

// ---------------------------------------------------------------------------
__device__ __forceinline__ uint32_t smem_u32(const void* p) {
    uint32_t a;
    asm("{ .reg .u64 t; cvta.to.shared.u64 t, %1; cvt.u32.u64 %0, t; }" : "=r"(a) : "l"(p));
    return a;
}
#define CP16(s, g) asm volatile("cp.async.cg.shared.global [%0], [%1], 16;" :: "r"(s), "l"(g))
#define CP_COMMIT() asm volatile("cp.async.commit_group;" ::: "memory")
#define CP_WAIT0()  asm volatile("cp.async.wait_group 0;" ::: "memory")
#define CP_WAIT1()  asm volatile("cp.async.wait_group 1;" ::: "memory")

__device__ __forceinline__ void ldsm4(uint32_t* r, uint32_t a) {
    asm volatile("ldmatrix.sync.aligned.m8n8.x4.shared.b16 {%0,%1,%2,%3}, [%4];"
                 : "=r"(r[0]), "=r"(r[1]), "=r"(r[2]), "=r"(r[3]) : "r"(a));
}
__device__ __forceinline__ void ldsm4t(uint32_t* r, uint32_t a) {
    asm volatile("ldmatrix.sync.aligned.m8n8.x4.trans.shared.b16 {%0,%1,%2,%3}, [%4];"
                 : "=r"(r[0]), "=r"(r[1]), "=r"(r[2]), "=r"(r[3]) : "r"(a));
}
__device__ __forceinline__ void mma16816(float* c, const uint32_t* a, uint32_t b0, uint32_t b1) {
    asm volatile("mma.sync.aligned.m16n8k16.row.col.f32.f16.f16.f32 "
                 "{%0,%1,%2,%3}, {%4,%5,%6,%7}, {%8,%9}, {%0,%1,%2,%3};"
                 : "+f"(c[0]), "+f"(c[1]), "+f"(c[2]), "+f"(c[3])
                 : "r"(a[0]), "r"(a[1]), "r"(a[2]), "r"(a[3]), "r"(b0), "r"(b1));
}
__device__ __forceinline__ uint32_t packh2(float lo, float hi) {
    uint32_t r;
    asm("cvt.rn.f16x2.f32 %0, %1, %2;" : "=r"(r) : "f"(hi), "f"(lo));
    return r;
}
__device__ __forceinline__ uint32_t hmax2(uint32_t a, uint32_t b) {
    uint32_t r;
    asm("max.f16x2 %0, %1, %2;" : "=r"(r) : "r"(a), "r"(b));
    return r;
}
__device__ __forceinline__ uint32_t hsub2(uint32_t a, uint32_t b) {
    uint32_t r;
    asm("sub.rn.f16x2 %0, %1, %2;" : "=r"(r) : "r"(a), "r"(b));
    return r;
}
__device__ __forceinline__ uint32_t ex2h2(uint32_t a) {
    uint32_t r;
    asm("ex2.approx.f16x2 %0, %1;" : "=r"(r) : "r"(a));
    return r;
}
__device__ __forceinline__ float ex2f(float x) {
    float r;
    asm("ex2.approx.f32 %0, %1;" : "=f"(r) : "f"(x));
    return r;
}

// ---------------------------------------------------------------------------
__global__ void f2h(const float* __restrict__ src, __half* __restrict__ dst, int n4) {
    const int i = blockIdx.x * blockDim.x + threadIdx.x;
    if (i < n4) {
        const float4 v = ((const float4*)src)[i];
        ((uint32_t*)dst)[2 * i + 0] = packh2(v.x, v.y);
        ((uint32_t*)dst)[2 * i + 1] = packh2(v.z, v.w);
    }
}
__global__ void f2h4(const float* __restrict__ s0, const float* __restrict__ s1,
                     const float* __restrict__ s2, const float* __restrict__ s3,
                     __half* __restrict__ dst) {
    const int i = blockIdx.x * blockDim.x + threadIdx.x;   // 0..262143
    const float* src = (blockIdx.y == 0) ? s0 : (blockIdx.y == 1) ? s1
                      : (blockIdx.y == 2) ? s2 : s3;
    const float4 v = ((const float4*)src)[i];
    uint32_t* d = (uint32_t*)(dst + (size_t)blockIdx.y * 1048576);
    d[2 * i + 0] = packh2(v.x, v.y);
    d[2 * i + 1] = packh2(v.z, v.w);
}

// ---------------------------------------------------------------------------
// Shared GEMM mainloop: 128x128 tile, 3-stage cp.async, one barrier/stage,
// fragment-prefetch MMA stream, lane-const addressing. (unchanged from R8)
// ---------------------------------------------------------------------------
#define GS 32768
#define GEMM_SMEM (3 * GS)

struct GemmCtx {
    uint32_t sb;
    int tid, wid, lane, wm, wn;
};

__device__ __forceinline__ void gemm_mainloop(
    const GemmCtx& cx, const __half* __restrict__ A, const __half* __restrict__ W,
    int m0, int n0, float acc[2][8][4])
{
    const int tid = cx.tid, lane = cx.lane, wm = cx.wm, wn = cx.wn;
    const uint32_t sb = cx.sb;

    int goff[4], soff[4];
#pragma unroll
    for (int i = 0; i < 4; i++) {
        const int id = tid + (i << 8), r = id >> 3, c = id & 7;
        goff[i] = r * 1024 + c * 8;
        soff[i] = r * 128 + ((c * 16) ^ ((r & 7) << 4));
    }
    auto load_stage = [&](const __half* ga, const __half* gb, int buf) {
        const uint32_t sA = sb + buf * GS, sB = sA + 16384;
#pragma unroll
        for (int i = 0; i < 4; i++) CP16(sA + soff[i], ga + goff[i]);
#pragma unroll
        for (int i = 0; i < 4; i++) CP16(sB + soff[i], gb + goff[i]);
    };

    const __half* ap = A + (size_t)m0 * 1024;
    const __half* wp = W + (size_t)n0 * 1024;
    load_stage(ap, wp, 0); CP_COMMIT(); ap += 64; wp += 64;
    load_stage(ap, wp, 1); CP_COMMIT(); ap += 64; wp += 64;

    const int la15 = lane & 15;
    const int lbr  = ((lane >> 4) << 3) + (lane & 7);
    const uint32_t axy = (uint32_t)(((lane >> 4) << 4) ^ ((la15 & 7) << 4));
    const uint32_t bxy = (uint32_t)((((lane >> 3) & 1) << 4) ^ ((lbr & 7) << 4));
    const int aoff0 = (wm + la15) * 128, aoff1 = (wm + 16 + la15) * 128;
    const int boff  = (wn + lbr) * 128;

    int cbuf = 0, lbuf = 2;
    for (int s = 0; s < 16; s++) {
        if (s < 15) CP_WAIT1(); else CP_WAIT0();
        __syncthreads();
        if (s + 2 < 16) { load_stage(ap, wp, lbuf); CP_COMMIT(); ap += 64; wp += 64; }

        const uint32_t sA = sb + cbuf * GS, sB = sA + 16384;
        auto ldA = [&](uint32_t a[2][4], int kd) {
            const uint32_t kk = (uint32_t)(kd * 32) ^ axy;
            ldsm4(a[0], sA + aoff0 + kk);
            ldsm4(a[1], sA + aoff1 + kk);
        };
        auto ldB = [&](uint32_t b[4], int kd, int nt2) {
            ldsm4(b, sB + boff + nt2 * 2048 + ((uint32_t)(kd * 32) ^ bxy));
        };

        uint32_t a[2][2][4], b[2][4];
        ldA(a[0], 0);
        ldB(b[0], 0, 0);
#pragma unroll
        for (int step = 0; step < 16; step++) {
            const int kd = step >> 2, nt2 = step & 3;
            const int cb = step & 1, ab = kd & 1;
            if (step < 15) ldB(b[cb ^ 1], (step + 1) >> 2, (step + 1) & 3);
            if (nt2 == 1 && kd < 3) ldA(a[ab ^ 1], kd + 1);
#pragma unroll
            for (int mt = 0; mt < 2; mt++) {
                mma16816(acc[mt][nt2 * 2 + 0], a[ab][mt], b[cb][0], b[cb][1]);
                mma16816(acc[mt][nt2 * 2 + 1], a[ab][mt], b[cb][2], b[cb][3]);
            }
        }
        cbuf = (cbuf == 2) ? 0 : cbuf + 1;
        lbuf = (lbuf == 2) ? 0 : lbuf + 1;
    }
}

// Merged Q/K/V projection: grid.z selects weight/bias/output. fp16 head layout.
__global__ void __launch_bounds__(256, 2)
gemm_qkv(const __half* __restrict__ A, const __half* __restrict__ Wbase,
         const float* __restrict__ bq, const float* __restrict__ bk,
         const float* __restrict__ bv,
         __half* __restrict__ Cq, __half* __restrict__ Ck, __half* __restrict__ Cv)
{
    extern __shared__ char smem[];
    GemmCtx cx;
    cx.sb = smem_u32(smem);
    cx.tid = threadIdx.x; cx.wid = cx.tid >> 5; cx.lane = cx.tid & 31;
    cx.wm = (cx.wid & 3) << 5; cx.wn = (cx.wid >> 2) << 6;
    const int m0 = blockIdx.y << 7, n0 = blockIdx.x << 7;
    const int z = blockIdx.z;
    const __half* W = Wbase + ((size_t)z << 20);
    const float* bias = (z == 0) ? bq : (z == 1) ? bk : bv;
    __half* C = (z == 0) ? Cq : (z == 1) ? Ck : Cv;
    const float scale = (z == 0) ? CEXP : 1.0f;

    float acc[2][8][4];
#pragma unroll
    for (int mt = 0; mt < 2; mt++)
#pragma unroll
        for (int nt = 0; nt < 8; nt++)
#pragma unroll
            for (int c = 0; c < 4; c++) acc[mt][nt][c] = 0.f;

    gemm_mainloop(cx, A, W, m0, n0, acc);

    const int r0 = cx.lane >> 2, colq = (cx.lane & 3) * 2;
#pragma unroll
    for (int mt = 0; mt < 2; mt++) {
        const int row0 = m0 + cx.wm + mt * 16 + r0;
#pragma unroll
        for (int nt = 0; nt < 8; nt++) {
            const int col = n0 + cx.wn + nt * 8 + colq;
            const float2 bvv = *(const float2*)(bias + col);
            const float v0 = (acc[mt][nt][0] + bvv.x) * scale;
            const float v1 = (acc[mt][nt][1] + bvv.y) * scale;
            const float v2 = (acc[mt][nt][2] + bvv.x) * scale;
            const float v3 = (acc[mt][nt][3] + bvv.y) * scale;
            const int b = row0 >> 11, h = col >> 6, d = col & 63;
            const size_t hb = (size_t)(((b << 4) + h) << 11);
            *(uint32_t*)(C + (hb + (row0 & 2047)) * 64 + d)       = packh2(v0, v1);
            *(uint32_t*)(C + (hb + ((row0 + 8) & 2047)) * 64 + d) = packh2(v2, v3);
        }
    }
}

// Output projection: fp32 row-major out.
__global__ void __launch_bounds__(256, 2)
gemm_o(const __half* __restrict__ A, const __half* __restrict__ W,
       const float* __restrict__ bias, float* __restrict__ C)
{
    extern __shared__ char smem[];
    GemmCtx cx;
    cx.sb = smem_u32(smem);
    cx.tid = threadIdx.x; cx.wid = cx.tid >> 5; cx.lane = cx.tid & 31;
    cx.wm = (cx.wid & 3) << 5; cx.wn = (cx.wid >> 2) << 6;
    const int m0 = blockIdx.y << 7, n0 = blockIdx.x << 7;

    float acc[2][8][4];
#pragma unroll
    for (int mt = 0; mt < 2; mt++)
#pragma unroll
        for (int nt = 0; nt < 8; nt++)
#pragma unroll
            for (int c = 0; c < 4; c++) acc[mt][nt][c] = 0.f;

    gemm_mainloop(cx, A, W, m0, n0, acc);

    const int r0 = cx.lane >> 2, colq = (cx.lane & 3) * 2;
#pragma unroll
    for (int mt = 0; mt < 2; mt++) {
        const int row0 = m0 + cx.wm + mt * 16 + r0;
#pragma unroll
        for (int nt = 0; nt < 8; nt++) {
            const int col = n0 + cx.wn + nt * 8 + colq;
            const float2 bvv = *(const float2*)(bias + col);
            *(float2*)(C + (size_t)row0 * 1024 + col) =
                make_float2(acc[mt][nt][0] + bvv.x, acc[mt][nt][1] + bvv.y);
            *(float2*)(C + (size_t)(row0 + 8) * 1024 + col) =
                make_float2(acc[mt][nt][2] + bvv.x, acc[mt][nt][3] + bvv.y);
        }
    }
}

// ---------------------------------------------------------------------------
// Flash attention, fp16 HMMA, 64-key subtiles, 4-stage ring, one barrier per
// PAIR of tiles, fully f16x2-packed softmax (max/sub/ex2), warp-uniform
// rescale skip, 2 CTAs/SM.
// ---------------------------------------------------------------------------
#define FS 16384                     // bytes per KV stage (K 8K + V 8K), 64 keys
#define FLASH_SMEM (16384 + 4 * FS)  // Q 16K + 4 stages = 80K

__global__ void __launch_bounds__(256, 2)
flash_hmma(const __half* __restrict__ Q, const __half* __restrict__ K,
           const __half* __restrict__ V, __half* __restrict__ O)
{
    extern __shared__ char smem[];
    const uint32_t sb = smem_u32(smem);
    const uint32_t sQ = sb, sKV = sb + 16384;       // 4 stages of [K 8K | V 8K]
    const int tid = threadIdx.x, wid = tid >> 5, lane = tid & 31;
    const int q0 = blockIdx.x << 7, bh = blockIdx.y;
    const size_t base = (size_t)bh * (2048 * 64);
    const __half* Qb = Q + base + (size_t)q0 * 64;
    const uint32_t ONES = 0x3C003C00u;

    int g0, g1, s0, s1;
    {
        const int r0_ = tid >> 3, c_ = tid & 7;
        const int r1_ = (tid + 256) >> 3;
        g0 = r0_ * 64 + c_ * 8;  s0 = r0_ * 128 + ((c_ * 16) ^ ((r0_ & 7) << 4));
        g1 = r1_ * 64 + c_ * 8;  s1 = r1_ * 128 + ((c_ * 16) ^ ((r1_ & 7) << 4));
    }

#pragma unroll
    for (int i = 0; i < 4; i++) {                   // Q tile: 128 x 64 halves
        const int id = tid + (i << 8), r = id >> 3, c = id & 7;
        CP16(sQ + r * 128 + ((c * 16) ^ ((r & 7) << 4)), Qb + (size_t)r * 64 + c * 8);
    }
    auto load_kv = [&](const __half* kp, const __half* vp, int buf) {
        const uint32_t ks_ = sKV + buf * FS, vs_ = ks_ + 8192;
        CP16(ks_ + s0, kp + g0);
        CP16(ks_ + s1, kp + g1);
        CP16(vs_ + s0, vp + g0);
        CP16(vs_ + s1, vp + g1);
    };
    const __half* kp = K + base;
    const __half* vp = V + base;
    load_kv(kp, vp, 0); CP_COMMIT();                // g0 incl Q
    load_kv(kp + 4096, vp + 4096, 1); CP_COMMIT();
    kp += 8192; vp += 8192;
    CP_WAIT0();
    __syncthreads();

    uint32_t qf[4][4];
#pragma unroll
    for (int kd = 0; kd < 4; kd++) {
        const int r = (wid << 4) + (lane & 15);
        const int cb = kd * 32 + ((lane >> 4) << 4);
        ldsm4(qf[kd], sQ + r * 128 + (cb ^ ((r & 7) << 4)));
    }

    const int klr  = ((lane >> 4) << 3) + (lane & 7);
    const int koff = klr * 128;
    const uint32_t kxy = (uint32_t)((((lane >> 3) & 1) << 4) ^ ((klr & 7) << 4));
    const int voff = (lane & 15) * 128;
    const uint32_t vxy = (uint32_t)(((lane >> 4) << 4) ^ ((lane & 7) << 4));

    float oacc[8][4];
#pragma unroll
    for (int dn = 0; dn < 8; dn++)
#pragma unroll
        for (int c = 0; c < 4; c++) oacc[dn][c] = 0.f;
    uint32_t mrp = 0xFC00FC00u;                     // (-inf, -inf) running max
    float l0 = 0.f, l1 = 0.f;

    auto attn_tile = [&](uint32_t ks_, uint32_t vs_) {
        float sacc[8][4];
#pragma unroll
        for (int nt = 0; nt < 8; nt++)
#pragma unroll
            for (int c = 0; c < 4; c++) sacc[nt][c] = 0.f;
        {
            uint32_t b[2][4];
            auto ldK = [&](uint32_t* bb, int step) {
                const int kd = step >> 2, nt2 = step & 3;
                ldsm4(bb, ks_ + koff + nt2 * 2048 + ((uint32_t)(kd * 32) ^ kxy));
            };
            ldK(b[0], 0);
#pragma unroll
            for (int step = 0; step < 16; step++) {
                const int nt2 = step & 3, cb = step & 1, kd = step >> 2;
                if (step < 15) ldK(b[cb ^ 1], step + 1);
                mma16816(sacc[nt2 * 2 + 0], qf[kd], b[cb][0], b[cb][1]);
                mma16816(sacc[nt2 * 2 + 1], qf[kd], b[cb][2], b[cb][3]);
            }
        }

        // --- f16x2 softmax ---
        // pack scores (row0 pairs -> [0], row1 pairs -> [2]), aliased into sacc
#pragma unroll
        for (int nt = 0; nt < 8; nt++) {
            sacc[nt][0] = __uint_as_float(packh2(sacc[nt][0], sacc[nt][1]));
            sacc[nt][2] = __uint_as_float(packh2(sacc[nt][2], sacc[nt][3]));
        }
        // prefetch first V fragments: LDSM latency hides under softmax chain
        uint32_t vb[2][4];
        ldsm4t(vb[0], vs_ + voff + (0 ^ vxy));
        // per-thread max trees (packed, both elements of each pair)
        uint32_t t0 = hmax2(__float_as_uint(sacc[0][0]), __float_as_uint(sacc[1][0]));
        uint32_t t1 = hmax2(__float_as_uint(sacc[2][0]), __float_as_uint(sacc[3][0]));
        uint32_t t2 = hmax2(__float_as_uint(sacc[4][0]), __float_as_uint(sacc[5][0]));
        uint32_t t3 = hmax2(__float_as_uint(sacc[6][0]), __float_as_uint(sacc[7][0]));
        uint32_t m0 = hmax2(hmax2(t0, t1), hmax2(t2, t3));
        t0 = hmax2(__float_as_uint(sacc[0][2]), __float_as_uint(sacc[1][2]));
        t1 = hmax2(__float_as_uint(sacc[2][2]), __float_as_uint(sacc[3][2]));
        t2 = hmax2(__float_as_uint(sacc[4][2]), __float_as_uint(sacc[5][2]));
        t3 = hmax2(__float_as_uint(sacc[6][2]), __float_as_uint(sacc[7][2]));
        uint32_t m1 = hmax2(hmax2(t0, t1), hmax2(t2, t3));
        m0 = hmax2(m0, __byte_perm(m0, 0, 0x1032));   // fold halves (row0)
        m1 = hmax2(m1, __byte_perm(m1, 0, 0x1032));   // fold halves (row1)
        uint32_t mp = __byte_perm(m0, m1, 0x7610);    // (row0max, row1max)
        mp = hmax2(mp, __shfl_xor_sync(0xffffffffu, mp, 1));
        mp = hmax2(mp, __shfl_xor_sync(0xffffffffu, mp, 2));
        const uint32_t mold = mrp;
        const uint32_t mn = hmax2(mold, mp);
        mrp = mn;
        // alpha = 2^(mold - mn), packed; exact 1.0 when unchanged
        const uint32_t alp = ex2h2(hsub2(mold, mn));
        const float2 alf = __half22float2(*(const __half2*)&alp);
        if (!__all_sync(0xffffffffu, mn == mold)) {
#pragma unroll
            for (int dn = 0; dn < 8; dn++) {
                oacc[dn][0] *= alf.x; oacc[dn][1] *= alf.x;
                oacc[dn][2] *= alf.y; oacc[dn][3] *= alf.y;
            }
        }
        // exp: packed sub + f16x2 ex2 (P stays packed fp16 in sacc aliases)
        const uint32_t mn0 = __byte_perm(mn, 0, 0x1010);
        const uint32_t mn1 = __byte_perm(mn, 0, 0x3232);
#pragma unroll
        for (int nt = 0; nt < 8; nt++) {
            sacc[nt][0] = __uint_as_float(ex2h2(hsub2(__float_as_uint(sacc[nt][0]), mn0)));
            sacc[nt][2] = __uint_as_float(ex2h2(hsub2(__float_as_uint(sacc[nt][2]), mn1)));
        }

        // O += P V; row sums via ones-B HMMA
        float rs[4] = {0.f, 0.f, 0.f, 0.f};
        {
            uint32_t a[4];
            auto ldVt = [&](uint32_t* bb, int step) {
                const int ks = step >> 2, dn2 = step & 3;
                ldsm4t(bb, vs_ + voff + ks * 2048 + ((uint32_t)(dn2 * 32) ^ vxy));
            };
#pragma unroll
            for (int step = 0; step < 16; step++) {
                const int ks = step >> 2, dn2 = step & 3, cb = step & 1;
                if (step < 15) ldVt(vb[cb ^ 1], step + 1);
                if (dn2 == 0) {
                    a[0] = __float_as_uint(sacc[2 * ks][0]);
                    a[1] = __float_as_uint(sacc[2 * ks][2]);
                    a[2] = __float_as_uint(sacc[2 * ks + 1][0]);
                    a[3] = __float_as_uint(sacc[2 * ks + 1][2]);
                    mma16816(rs, a, ONES, ONES);
                }
                mma16816(oacc[dn2 * 2 + 0], a, vb[cb][0], vb[cb][1]);
                mma16816(oacc[dn2 * 2 + 1], a, vb[cb][2], vb[cb][3]);
            }
        }
        l0 = l0 * alf.x + rs[0];
        l1 = l1 * alf.y + rs[2];
    };

    // main loop: 16 pairs of 64-key tiles; one wait+barrier per pair
    for (int p = 0; p < 16; p++) {
        if (p > 0) {
            CP_WAIT0();
            __syncthreads();
        }
        if (p < 15) {
            load_kv(kp, vp, (2 * p + 2) & 3); CP_COMMIT();
            load_kv(kp + 4096, vp + 4096, (2 * p + 3) & 3); CP_COMMIT();
            kp += 8192; vp += 8192;
        }
        const uint32_t b0 = sKV + ((2 * p) & 3) * FS;
        const uint32_t b1 = sKV + ((2 * p + 1) & 3) * FS;
        attn_tile(b0, b0 + 8192);
        attn_tile(b1, b1 + 8192);
    }

    // normalize + write packed [b][s][h*64+d] fp16
    const int b_ = bh >> 4, h_ = bh & 15;
    __half* Ob = O + ((size_t)b_ * 2048 + q0) * 1024 + h_ * 64;
    const float inv0 = 1.f / l0, inv1 = 1.f / l1;
    const int r0 = (wid << 4) + (lane >> 2), colq = (lane & 3) * 2;
#pragma unroll
    for (int dn = 0; dn < 8; dn++) {
        const int col = dn * 8 + colq;
        *(uint32_t*)(Ob + (size_t)r0 * 1024 + col) =
            packh2(oacc[dn][0] * inv0, oacc[dn][1] * inv0);
        *(uint32_t*)(Ob + (size_t)(r0 + 8) * 1024 + col) =
            packh2(oacc[dn][2] * inv1, oacc[dn][3] * inv1);
    }
}

// ---------------------------------------------------------------------------
extern "C" void kernel_launch(void* const* d_in, const int* in_sizes, int n_in,
                              void* d_out, int out_size)
{
    const float* x  = (const float*)d_in[0];
    const float* wq = (const float*)d_in[1];
    const float* bq = (const float*)d_in[2];
    const float* wk = (const float*)d_in[3];
    const float* bk = (const float*)d_in[4];
    const float* wv = (const float*)d_in[5];
    const float* bv = (const float*)d_in[6];
    const float* wo = (const float*)d_in[7];
    const float* bo = (const float*)d_in[8];
    float* out = (float*)d_out;

    __half *xh, *wh, *qh, *kh, *vh, *aoh;
    cudaGetSymbolAddress((void**)&xh,  g_xh);
    cudaGetSymbolAddress((void**)&wh,  g_wh);
    cudaGetSymbolAddress((void**)&qh,  g_qh);
    cudaGetSymbolAddress((void**)&kh,  g_kh);
    cudaGetSymbolAddress((void**)&vh,  g_vh);
    cudaGetSymbolAddress((void**)&aoh, g_aoh);

    cudaFuncSetAttribute(gemm_qkv, cudaFuncAttributeMaxDynamicSharedMemorySize, GEMM_SMEM);
    cudaFuncSetAttribute(gemm_o,   cudaFuncAttributeMaxDynamicSharedMemorySize, GEMM_SMEM);
    cudaFuncSetAttribute(flash_hmma, cudaFuncAttributeMaxDynamicSharedMemorySize, FLASH_SMEM);

    f2h<<<8192, 256>>>(x, xh, 2097152);
    f2h4<<<dim3(1024, 4), 256>>>(wq, wk, wv, wo, wh);

    gemm_qkv<<<dim3(8, 64, 3), 256, GEMM_SMEM>>>(xh, wh, bq, bk, bv, qh, kh, vh);
    flash_hmma<<<dim3(16, 64), 256, FLASH_SMEM>>>(qh, kh, vh, aoh);
    gemm_o<<<dim3(8, 64), 256, GEMM_SMEM>>>(aoh, wh + 3145728, bo, out);
}